// round 10
// baseline (speedup 1.0000x reference)
#include <cuda_runtime.h>
#include <cuda_fp16.h>
#include <cstdint>
#include <cmath>

#define BATCH 2
#define CH    512
#define NPIX  4096
#define NFOLD (BATCH * NPIX)     // 8192
#define EPS   1e-6f

// ------------------------- scratch (device globals) -------------------------
static __device__ float2 g_stats[BATCH * 32];
static __device__ __half g_w[4 * CH * CH];                     // q,k,v,o stacked
static __device__ __half g_hnT[(size_t)NFOLD * CH];
static __device__ __half g_qT[(size_t)NFOLD * CH];
static __device__ __half g_kT[(size_t)NFOLD * CH];
static __device__ __half g_v[(size_t)BATCH * CH * NPIX];
static __device__ __half g_s[(size_t)BATCH * NPIX * NPIX];     // fp16 scores, 67 MB
static __device__ __half g_at[(size_t)BATCH * NPIX * NPIX];    // 67 MB
static __device__ __half g_oT[(size_t)NFOLD * CH];

// ------------------------- small helpers -------------------------
__device__ __forceinline__ void cp16(uint32_t s, const void* g) {
    asm volatile("cp.async.cg.shared.global [%0], [%1], 16;" :: "r"(s), "l"(g));
}

#define CP_COMMIT() asm volatile("cp.async.commit_group;" ::: "memory")

#define LDSM4(R, addr) \
    asm volatile("ldmatrix.sync.aligned.m8n8.x4.shared.b16 {%0,%1,%2,%3}, [%4];" \
        : "=r"((R)[0]), "=r"((R)[1]), "=r"((R)[2]), "=r"((R)[3]) : "r"(addr))

#define MMA16816(D, A, B) \
    asm volatile("mma.sync.aligned.m16n8k16.row.col.f32.f16.f16.f32 " \
        "{%0,%1,%2,%3}, {%4,%5,%6,%7}, {%8,%9}, {%0,%1,%2,%3};" \
        : "+f"((D)[0]), "+f"((D)[1]), "+f"((D)[2]), "+f"((D)[3]) \
        : "r"((A)[0]), "r"((A)[1]), "r"((A)[2]), "r"((A)[3]), \
          "r"((B)[0]), "r"((B)[1]))

__device__ __forceinline__ uint32_t smem_u32(const void* p) {
    uint32_t a;
    asm("{ .reg .u64 t; cvta.to.shared.u64 t, %1; cvt.u32.u64 %0, t; }"
        : "=r"(a) : "l"(p));
    return a;
}

__device__ __forceinline__ __half2 h2(float a, float b) {
    return __halves2half2(__float2half_rn(a), __float2half_rn(b));
}

// ------------------- all W fp32 -> fp16 (one launch, stacked) -------------------
__global__ void __launch_bounds__(256) convert_w4_kernel(
    const float* __restrict__ w0, const float* __restrict__ w1,
    const float* __restrict__ w2, const float* __restrict__ w3)
{
    const float* src = (blockIdx.y == 0) ? w0 : (blockIdx.y == 1) ? w1
                     : (blockIdx.y == 2) ? w2 : w3;
    int i = blockIdx.x * 256 + threadIdx.x;
    float4 v = ((const float4*)src)[i];
    size_t e = (size_t)blockIdx.y * CH * CH + (size_t)i * 4;
    __half2* d = (__half2*)(g_w + e);
    d[0] = h2(v.x, v.y);
    d[1] = h2(v.z, v.w);
}

// ------------------------- GroupNorm stats -------------------------
__global__ void __launch_bounds__(256) gn_stats_kernel(const float* __restrict__ x)
{
    const int g = blockIdx.x, b = blockIdx.y;
    const size_t base = ((size_t)b * CH + (size_t)g * 16) * NPIX;
    const float4* x4 = (const float4*)(x + base);
    const int n4 = 16 * NPIX / 4;

    float s = 0.f, ss = 0.f;
    for (int i = threadIdx.x; i < n4; i += 256) {
        float4 v = x4[i];
        s  += v.x + v.y + v.z + v.w;
        ss += v.x * v.x + v.y * v.y + v.z * v.z + v.w * v.w;
    }
    __shared__ float rs[8], rss[8];
    #pragma unroll
    for (int o = 16; o; o >>= 1) {
        s  += __shfl_xor_sync(0xffffffffu, s, o);
        ss += __shfl_xor_sync(0xffffffffu, ss, o);
    }
    const int lane = threadIdx.x & 31, wid = threadIdx.x >> 5;
    if (lane == 0) { rs[wid] = s; rss[wid] = ss; }
    __syncthreads();
    if (threadIdx.x == 0) {
        float ts = 0.f, tss = 0.f;
        #pragma unroll
        for (int i = 0; i < 8; i++) { ts += rs[i]; tss += rss[i]; }
        const float inv_n = 1.0f / (16 * NPIX);
        float mean = ts * inv_n;
        float var = tss * inv_n - mean * mean;
        g_stats[b * 32 + g] = make_float2(mean, rsqrtf(var + EPS));
    }
}

// ---------- transpose + normalize + fp16 convert:  x[b,c,n] -> hnT[b*N+n, c] ----------
__global__ void __launch_bounds__(256) tnc_kernel(
    const float* __restrict__ x, const float* __restrict__ gamma,
    const float* __restrict__ beta)
{
    __shared__ float tile[32][33];
    const int b = blockIdx.z;
    const int n0 = blockIdx.x * 32, c0 = blockIdx.y * 32;
    const int tx = threadIdx.x & 31, ty = threadIdx.x >> 5;   // 32 x 8

    #pragma unroll
    for (int j = 0; j < 4; j++) {
        int c = c0 + ty + j * 8;
        float2 st = g_stats[b * 32 + (c >> 4)];
        float gm = gamma[c] * st.y;
        float bt = beta[c] - st.x * gm;
        float v = x[((size_t)(b * CH + c)) * NPIX + n0 + tx];
        tile[ty + j * 8][tx] = v * gm + bt;
    }
    __syncthreads();
    #pragma unroll
    for (int j = 0; j < 4; j++) {
        int n = n0 + ty + j * 8;
        float v = tile[tx][ty + j * 8];
        size_t a = ((size_t)(b * NPIX + n)) * CH + c0 + tx;
        g_hnT[a] = __float2half_rn(v);
    }
}

// ------------------------- mma.sync GEMM -------------------------
// D[m,n] = sum_k A[m,k]*B[n,k], K-major fp16, fp32 acc.
// CTA: 128(M) x 128(N), K-chunk 64, XOR-swizzled 128B rows, 4-stage cp.async.
// 256 thr = 8 warps (2M x 4N), warp tile 64x32. 1 CTA/SM, high regs,
// explicit fragment double-buffering across ks for LDSM/MMA overlap.
#define OFF_B    16384
#define STAGE    32768
#define SMEM_GEMM (4 * STAGE)    // 131072; epilogue reuses 66048

enum { EPI_QKV = 0, EPI_S = 1, EPI_AV = 2, EPI_P = 3 };

__device__ __forceinline__ void load_stage(
    uint32_t so, const __half* __restrict__ A, const __half* __restrict__ B,
    int K, int k0, int tid)
{
    #pragma unroll
    for (int j = 0; j < 8; j++) {
        int i = tid + j * 256;                 // 0..2047
        int r = (i >> 3) & 127;                // row within region
        int c = i & 7;                         // 16B unit
        const __half* src = ((j < 4) ? A : B) + r * K + k0 + c * 8;
        uint32_t dst = so + ((j < 4) ? 0u : (uint32_t)OFF_B)
                     + (uint32_t)r * 128 + (uint32_t)((c ^ (r & 7)) << 4);
        cp16(dst, src);
    }
}

__device__ __forceinline__ void ld_frag(
    uint32_t a_row, uint32_t b_row, int ks, int ua, int ub, int ra7, int rb7,
    uint32_t (&FA)[4][4], uint32_t (&FB)[2][4])
{
    const uint32_t a_sw = (uint32_t)(((2 * ks + ua) ^ ra7) << 4);
    const uint32_t b_sw = (uint32_t)(((2 * ks + ub) ^ rb7) << 4);
    LDSM4(FA[0], a_row + a_sw);
    LDSM4(FA[1], a_row + a_sw + 16 * 128);
    LDSM4(FA[2], a_row + a_sw + 32 * 128);
    LDSM4(FA[3], a_row + a_sw + 48 * 128);
    LDSM4(FB[0], b_row + b_sw);
    LDSM4(FB[1], b_row + b_sw + 16 * 128);
}

__device__ __forceinline__ void do_mmas(
    uint32_t (&FA)[4][4], uint32_t (&FB)[2][4], float acc[4][4][4])
{
    #pragma unroll
    for (int mt = 0; mt < 4; mt++) {
        MMA16816(acc[mt][0], FA[mt], FB[0]);
        MMA16816(acc[mt][1], FA[mt], FB[0] + 2);
        MMA16816(acc[mt][2], FA[mt], FB[1]);
        MMA16816(acc[mt][3], FA[mt], FB[1] + 2);
    }
}

template<int EPI>
__global__ void __launch_bounds__(256, 1) gemm_mma(
    const __half* __restrict__ A, const __half* __restrict__ B,
    int K, size_t Az, size_t Bz,
    __half* __restrict__ O0, __half* __restrict__ O1, __half* __restrict__ O2,
    float* __restrict__ Ofp,
    const float* __restrict__ b0, const float* __restrict__ b1,
    const float* __restrict__ b2,
    const float* __restrict__ resid, float scale)
{
    extern __shared__ __align__(16) uint8_t gsm[];
    const uint32_t sbase = smem_u32(gsm);
    const int tid = threadIdx.x, lane = tid & 31, wid = tid >> 5;
    const int wm = (wid >> 2) * 64, wn = (wid & 3) * 32;
    const int bz = blockIdx.z;
    const int m0 = blockIdx.y * 128, n0 = blockIdx.x * 128;

    const __half* Ap = A + (size_t)bz * Az + (size_t)m0 * K;
    const __half* Bp = B + (size_t)bz * Bz + (size_t)n0 * K;

    const int ra = wm + (lane & 15);
    const int rb = wn + ((lane >> 4) << 3) + (lane & 7);
    const int ua = (lane >> 4);
    const int ub = ((lane >> 3) & 1);
    const int ra7 = ra & 7, rb7 = rb & 7;

    const int NT = K / 64;
    float acc[4][4][4] = {};
    uint32_t FA[2][4][4], FB[2][2][4];

    load_stage(sbase + 0 * STAGE, Ap, Bp, K, 0, tid);   CP_COMMIT();
    load_stage(sbase + 1 * STAGE, Ap, Bp, K, 64, tid);  CP_COMMIT();
    load_stage(sbase + 2 * STAGE, Ap, Bp, K, 128, tid); CP_COMMIT();

    for (int t = 0; t < NT; t++) {
        const int rem = NT - 1 - t;
        if (rem >= 2)      { asm volatile("cp.async.wait_group 2;" ::: "memory"); }
        else if (rem == 1) { asm volatile("cp.async.wait_group 1;" ::: "memory"); }
        else               { asm volatile("cp.async.wait_group 0;" ::: "memory"); }
        __syncthreads();
        if (t + 3 < NT) {
            load_stage(sbase + (uint32_t)((t + 3) & 3) * STAGE, Ap, Bp, K,
                       (t + 3) * 64, tid);
            CP_COMMIT();
        }
        const uint32_t so = sbase + (uint32_t)(t & 3) * STAGE;
        const uint32_t a_row = so + (uint32_t)ra * 128;
        const uint32_t b_row = so + OFF_B + (uint32_t)rb * 128;

        ld_frag(a_row, b_row, 0, ua, ub, ra7, rb7, FA[0], FB[0]);
        #pragma unroll
        for (int ks = 0; ks < 4; ks++) {
            if (ks < 3)
                ld_frag(a_row, b_row, ks + 1, ua, ub, ra7, rb7,
                        FA[(ks + 1) & 1], FB[(ks + 1) & 1]);
            do_mmas(FA[ks & 1], FB[ks & 1], acc);
        }
    }
    __syncthreads();

    // -------- epilogue: single pass through 128x129 fp32 smem --------
    float* Sf = (float*)gsm;
    const int grp = lane >> 2, tg = lane & 3;
    #pragma unroll
    for (int mt = 0; mt < 4; mt++) {
        #pragma unroll
        for (int nf = 0; nf < 4; nf++) {
            int m = wm + mt * 16 + grp;
            int n = wn + nf * 8 + tg * 2;
            Sf[m * 129 + n]           = acc[mt][nf][0];
            Sf[m * 129 + n + 1]       = acc[mt][nf][1];
            Sf[(m + 8) * 129 + n]     = acc[mt][nf][2];
            Sf[(m + 8) * 129 + n + 1] = acc[mt][nf][3];
        }
    }
    __syncthreads();

    const int rr = tid >> 5;        // 0..7
    const int cc = tid & 31;        // 0..31
    const int wtype = m0 >> 9;      // QKV: 0=q,1=k,2=v
    const int mloc0 = m0 & (CH - 1);

    #pragma unroll 1
    for (int it = 0; it < 16; it++) {
        const int r = rr + it * 8;
        if (EPI == EPI_S) {
            const float* s = &Sf[r * 129 + cc * 4];
            size_t a = ((size_t)bz * NPIX + m0 + r) * NPIX + n0 + cc * 4;
            *(__half2*)&O0[a]     = h2(s[0], s[1]);
            *(__half2*)&O0[a + 2] = h2(s[2], s[3]);
        } else if (EPI == EPI_P) {
            const float bv = b0[m0 + r];
            size_t a = ((size_t)((n0 >> 12) * CH + m0 + r)) * NPIX
                     + (n0 & (NPIX - 1)) + cc * 4;
            float4 rd = *(const float4*)&resid[a];
            const float* s = &Sf[r * 129 + cc * 4];
            float4 o = make_float4(s[0] + bv + rd.x, s[1] + bv + rd.y,
                                   s[2] + bv + rd.z, s[3] + bv + rd.w);
            *(float4*)&Ofp[a] = o;
        } else if (EPI == EPI_AV) {
            size_t a = ((size_t)bz * NPIX + m0 + r) * CH + n0 + cc * 4;
            const float* s = &Sf[r * 129 + cc * 4];
            *(__half2*)&O0[a]     = h2(s[0], s[1]);
            *(__half2*)&O0[a + 2] = h2(s[2], s[3]);
        } else {    // EPI_QKV
            if (wtype == 2) {
                const float bv = b2[mloc0 + r];
                size_t a = ((size_t)((n0 >> 12) * CH + mloc0 + r)) * NPIX
                         + (n0 & (NPIX - 1)) + cc * 4;
                const float* s = &Sf[r * 129 + cc * 4];
                *(__half2*)&O2[a]     = h2(s[0] + bv, s[1] + bv);
                *(__half2*)&O2[a + 2] = h2(s[2] + bv, s[3] + bv);
            } else {
                __half* Op = (wtype == 0) ? O0 : O1;
                const float* bp = (wtype == 0) ? b0 : b1;
                const float sc = (wtype == 0) ? scale : 1.0f;
                size_t a = ((size_t)n0 + r) * CH + mloc0 + cc * 4;
                float v0 = (Sf[(cc * 4 + 0) * 129 + r] + bp[mloc0 + cc * 4 + 0]) * sc;
                float v1 = (Sf[(cc * 4 + 1) * 129 + r] + bp[mloc0 + cc * 4 + 1]) * sc;
                float v2 = (Sf[(cc * 4 + 2) * 129 + r] + bp[mloc0 + cc * 4 + 2]) * sc;
                float v3 = (Sf[(cc * 4 + 3) * 129 + r] + bp[mloc0 + cc * 4 + 3]) * sc;
                *(__half2*)&Op[a]     = h2(v0, v1);
                *(__half2*)&Op[a + 2] = h2(v2, v3);
            }
        }
    }
}

// -------------- softmax rows of fp16 scores -> attn fp16 --------------
__global__ void __launch_bounds__(256) softmax_kernel()
{
    const size_t row = blockIdx.x;       // 0 .. NFOLD-1
    const uint4* p = (const uint4*)(g_s + row * NPIX);   // 512 uint4 (8 halves each)
    uint4* oh = (uint4*)(g_at + row * NPIX);
    const int t = threadIdx.x;
    const int lane = t & 31, wid = t >> 5;

    float v[16];
    float mx = -1e30f;
    #pragma unroll
    for (int j = 0; j < 2; j++) {
        uint4 u = p[t + 256 * j];
        const uint32_t* q = (const uint32_t*)&u;
        #pragma unroll
        for (int w = 0; w < 4; w++) {
            float2 f = __half22float2(*(const __half2*)&q[w]);
            v[j * 8 + w * 2 + 0] = f.x;
            v[j * 8 + w * 2 + 1] = f.y;
            mx = fmaxf(mx, fmaxf(f.x, f.y));
        }
    }
    __shared__ float red[8];
    __shared__ float s_mx, s_sum;
    #pragma unroll
    for (int o = 16; o; o >>= 1) mx = fmaxf(mx, __shfl_xor_sync(0xffffffffu, mx, o));
    if (lane == 0) red[wid] = mx;
    __syncthreads();
    if (t == 0) {
        float m = red[0];
        #pragma unroll
        for (int i = 1; i < 8; i++) m = fmaxf(m, red[i]);
        s_mx = m;
    }
    __syncthreads();
    mx = s_mx;

    float sum = 0.f;
    #pragma unroll
    for (int i = 0; i < 16; i++) {
        v[i] = __expf(v[i] - mx);
        sum += v[i];
    }
    #pragma unroll
    for (int o = 16; o; o >>= 1) sum += __shfl_xor_sync(0xffffffffu, sum, o);
    if (lane == 0) red[wid] = sum;
    __syncthreads();
    if (t == 0) {
        float s = 0.f;
        #pragma unroll
        for (int i = 0; i < 8; i++) s += red[i];
        s_sum = s;
    }
    __syncthreads();
    const float inv = 1.0f / s_sum;

    #pragma unroll
    for (int j = 0; j < 2; j++) {
        uint4 u;
        uint32_t* q = (uint32_t*)&u;
        #pragma unroll
        for (int w = 0; w < 4; w++) {
            __half2 hh = h2(v[j * 8 + w * 2] * inv, v[j * 8 + w * 2 + 1] * inv);
            q[w] = *(uint32_t*)&hh;
        }
        oh[t + 256 * j] = u;
    }
}

// ------------------------- launcher -------------------------
extern "C" void kernel_launch(void* const* d_in, const int* in_sizes, int n_in,
                              void* d_out, int out_size)
{
    const float* x     = (const float*)d_in[0];
    const float* gamma = (const float*)d_in[1];
    const float* beta  = (const float*)d_in[2];
    const float* Wq    = (const float*)d_in[3];
    const float* bq    = (const float*)d_in[4];
    const float* Wk    = (const float*)d_in[5];
    const float* bk    = (const float*)d_in[6];
    const float* Wv    = (const float*)d_in[7];
    const float* bv    = (const float*)d_in[8];
    const float* Wo    = (const float*)d_in[9];
    const float* bo    = (const float*)d_in[10];
    float* out = (float*)d_out;

    void* p;
    __half *w, *hnT, *qT, *kT, *v, *at, *oT, *sh;
    cudaGetSymbolAddress(&p, g_w);    w   = (__half*)p;
    cudaGetSymbolAddress(&p, g_hnT);  hnT = (__half*)p;
    cudaGetSymbolAddress(&p, g_qT);   qT  = (__half*)p;
    cudaGetSymbolAddress(&p, g_kT);   kT  = (__half*)p;
    cudaGetSymbolAddress(&p, g_v);    v   = (__half*)p;
    cudaGetSymbolAddress(&p, g_at);   at  = (__half*)p;
    cudaGetSymbolAddress(&p, g_oT);   oT  = (__half*)p;
    cudaGetSymbolAddress(&p, g_s);    sh  = (__half*)p;

    cudaFuncSetAttribute(gemm_mma<EPI_QKV>, cudaFuncAttributeMaxDynamicSharedMemorySize, SMEM_GEMM);
    cudaFuncSetAttribute(gemm_mma<EPI_S>,   cudaFuncAttributeMaxDynamicSharedMemorySize, SMEM_GEMM);
    cudaFuncSetAttribute(gemm_mma<EPI_AV>,  cudaFuncAttributeMaxDynamicSharedMemorySize, SMEM_GEMM);
    cudaFuncSetAttribute(gemm_mma<EPI_P>,   cudaFuncAttributeMaxDynamicSharedMemorySize, SMEM_GEMM);

    const float scale = 1.0f / sqrtf((float)CH);
    const size_t WN = (size_t)CH * CH;

    // weights fp32 -> fp16 (stacked q,k,v,o)
    convert_w4_kernel<<<dim3(WN / 4 / 256, 4), 256>>>(Wq, Wk, Wv, Wo);
    // GroupNorm + transpose -> hnT
    gn_stats_kernel<<<dim3(32, BATCH), 256>>>(x);
    tnc_kernel<<<dim3(NPIX / 32, CH / 32, BATCH), 256>>>(x, gamma, beta);

    // fused QKV GEMM: A = stacked W [1536, 512], B = hnT [NFOLD, 512]
    dim3 gQKV(NFOLD / 128, 3 * CH / 128, 1);     // 64 x 12 = 768 CTAs
    gemm_mma<EPI_QKV><<<gQKV, 256, SMEM_GEMM>>>(
        w, hnT, CH, 0, 0,
        qT, kT, v, nullptr, bq, bk, bv, nullptr, scale);

    // scores (scale folded into q) -> fp16
    dim3 gS(NPIX / 128, NPIX / 128, BATCH);      // 32 x 32 x 2 = 2048 CTAs
    gemm_mma<EPI_S><<<gS, 256, SMEM_GEMM>>>(
        qT, kT, CH, (size_t)NPIX * CH, (size_t)NPIX * CH,
        sh, nullptr, nullptr, nullptr, nullptr, nullptr, nullptr, nullptr, 0.f);

    // softmax -> attn fp16
    softmax_kernel<<<NFOLD, 256>>>();

    // AV: D[i,c] = sum_j attn[i,j] v[c,j] -> oT row-major [NFOLD, CH]
    dim3 gAV(CH / 128, NPIX / 128, BATCH);       // 4 x 32 x 2 = 256 CTAs
    gemm_mma<EPI_AV><<<gAV, 256, SMEM_GEMM>>>(
        at, v, NPIX, (size_t)NPIX * NPIX, (size_t)CH * NPIX,
        oT, nullptr, nullptr, nullptr, nullptr, nullptr, nullptr, nullptr, 0.f);

    // proj + bias + residual -> out
    dim3 gP(NFOLD / 128, CH / 128, 1);           // 64 x 4 = 256 CTAs
    gemm_mma<EPI_P><<<gP, 256, SMEM_GEMM>>>(
        w + 3 * WN, oT, CH, 0, 0,
        nullptr, nullptr, nullptr, out, bo, nullptr, nullptr, x, 0.f);

    (void)in_sizes; (void)n_in; (void)out_size;
}

// round 13
// speedup vs baseline: 1.1758x; 1.1758x over previous
#include <cuda_runtime.h>
#include <cuda_fp16.h>
#include <cstdint>
#include <cmath>

#define BATCH 2
#define CH    512
#define NPIX  4096
#define NFOLD (BATCH * NPIX)     // 8192
#define EPS   1e-6f

// ------------------------- scratch (device globals) -------------------------
static __device__ float2 g_stats[BATCH * 32];
static __device__ __half g_w[4 * CH * CH];                     // q,k,v,o stacked
static __device__ __half g_hnT[(size_t)NFOLD * CH];
static __device__ __half g_qT[(size_t)NFOLD * CH];
static __device__ __half g_kT[(size_t)NFOLD * CH];
static __device__ __half g_v[(size_t)BATCH * CH * NPIX];
static __device__ __half g_s[(size_t)BATCH * NPIX * NPIX];     // fp16 scores, 67 MB
static __device__ __half g_at[(size_t)BATCH * NPIX * NPIX];    // 67 MB
static __device__ __half g_oT[(size_t)NFOLD * CH];

// ------------------------- small helpers -------------------------
__device__ __forceinline__ void cp16(uint32_t s, const void* g) {
    asm volatile("cp.async.cg.shared.global [%0], [%1], 16;" :: "r"(s), "l"(g));
}

#define CP_COMMIT() asm volatile("cp.async.commit_group;" ::: "memory")

#define LDSM4(R, addr) \
    asm volatile("ldmatrix.sync.aligned.m8n8.x4.shared.b16 {%0,%1,%2,%3}, [%4];" \
        : "=r"((R)[0]), "=r"((R)[1]), "=r"((R)[2]), "=r"((R)[3]) : "r"(addr))

#define MMA16816(D, A, B) \
    asm volatile("mma.sync.aligned.m16n8k16.row.col.f32.f16.f16.f32 " \
        "{%0,%1,%2,%3}, {%4,%5,%6,%7}, {%8,%9}, {%0,%1,%2,%3};" \
        : "+f"((D)[0]), "+f"((D)[1]), "+f"((D)[2]), "+f"((D)[3]) \
        : "r"((A)[0]), "r"((A)[1]), "r"((A)[2]), "r"((A)[3]), \
          "r"((B)[0]), "r"((B)[1]))

__device__ __forceinline__ uint32_t smem_u32(const void* p) {
    uint32_t a;
    asm("{ .reg .u64 t; cvta.to.shared.u64 t, %1; cvt.u32.u64 %0, t; }"
        : "=r"(a) : "l"(p));
    return a;
}

__device__ __forceinline__ __half2 h2(float a, float b) {
    return __halves2half2(__float2half_rn(a), __float2half_rn(b));
}

// ------------------- all W fp32 -> fp16 (one launch, stacked) -------------------
__global__ void __launch_bounds__(256) convert_w4_kernel(
    const float* __restrict__ w0, const float* __restrict__ w1,
    const float* __restrict__ w2, const float* __restrict__ w3)
{
    const float* src = (blockIdx.y == 0) ? w0 : (blockIdx.y == 1) ? w1
                     : (blockIdx.y == 2) ? w2 : w3;
    int i = blockIdx.x * 256 + threadIdx.x;
    float4 v = ((const float4*)src)[i];
    size_t e = (size_t)blockIdx.y * CH * CH + (size_t)i * 4;
    __half2* d = (__half2*)(g_w + e);
    d[0] = h2(v.x, v.y);
    d[1] = h2(v.z, v.w);
}

// ------------------------- GroupNorm stats -------------------------
__global__ void __launch_bounds__(256) gn_stats_kernel(const float* __restrict__ x)
{
    const int g = blockIdx.x, b = blockIdx.y;
    const size_t base = ((size_t)b * CH + (size_t)g * 16) * NPIX;
    const float4* x4 = (const float4*)(x + base);
    const int n4 = 16 * NPIX / 4;

    float s = 0.f, ss = 0.f;
    for (int i = threadIdx.x; i < n4; i += 256) {
        float4 v = x4[i];
        s  += v.x + v.y + v.z + v.w;
        ss += v.x * v.x + v.y * v.y + v.z * v.z + v.w * v.w;
    }
    __shared__ float rs[8], rss[8];
    #pragma unroll
    for (int o = 16; o; o >>= 1) {
        s  += __shfl_xor_sync(0xffffffffu, s, o);
        ss += __shfl_xor_sync(0xffffffffu, ss, o);
    }
    const int lane = threadIdx.x & 31, wid = threadIdx.x >> 5;
    if (lane == 0) { rs[wid] = s; rss[wid] = ss; }
    __syncthreads();
    if (threadIdx.x == 0) {
        float ts = 0.f, tss = 0.f;
        #pragma unroll
        for (int i = 0; i < 8; i++) { ts += rs[i]; tss += rss[i]; }
        const float inv_n = 1.0f / (16 * NPIX);
        float mean = ts * inv_n;
        float var = tss * inv_n - mean * mean;
        g_stats[b * 32 + g] = make_float2(mean, rsqrtf(var + EPS));
    }
}

// ---------- transpose + normalize + fp16 convert:  x[b,c,n] -> hnT[b*N+n, c] ----------
__global__ void __launch_bounds__(256) tnc_kernel(
    const float* __restrict__ x, const float* __restrict__ gamma,
    const float* __restrict__ beta)
{
    __shared__ float tile[32][33];
    const int b = blockIdx.z;
    const int n0 = blockIdx.x * 32, c0 = blockIdx.y * 32;
    const int tx = threadIdx.x & 31, ty = threadIdx.x >> 5;   // 32 x 8

    #pragma unroll
    for (int j = 0; j < 4; j++) {
        int c = c0 + ty + j * 8;
        float2 st = g_stats[b * 32 + (c >> 4)];
        float gm = gamma[c] * st.y;
        float bt = beta[c] - st.x * gm;
        float v = x[((size_t)(b * CH + c)) * NPIX + n0 + tx];
        tile[ty + j * 8][tx] = v * gm + bt;
    }
    __syncthreads();
    #pragma unroll
    for (int j = 0; j < 4; j++) {
        int n = n0 + ty + j * 8;
        float v = tile[tx][ty + j * 8];
        size_t a = ((size_t)(b * NPIX + n)) * CH + c0 + tx;
        g_hnT[a] = __float2half_rn(v);
    }
}

// ------------------------- mma.sync GEMM (fp16, 8 warps, 64x32 warp tile) -------------------------
// D[m,n] = sum_k A[m,k]*B[n,k], K-major fp16, fp32 acc.
// CTA: 128(M) x 128(N), K-chunk 64, XOR-swizzled 128B rows, 3-stage cp.async.
// 256 thr = 8 warps in 2(M) x 4(N); warp tile 64x32. __launch_bounds__(256,2).
#define OFF_B    16384
#define STAGE    32768
#define SMEM_GEMM (3 * STAGE)    // 98304; epilogue reuses 66048

enum { EPI_QKV = 0, EPI_S = 1, EPI_AV = 2, EPI_P = 3 };

__device__ __forceinline__ void load_stage(
    uint32_t so, const __half* __restrict__ A, const __half* __restrict__ B,
    int K, int k0, int tid)
{
    #pragma unroll
    for (int j = 0; j < 8; j++) {
        int i = tid + j * 256;                 // 0..2047
        int r = (i >> 3) & 127;                // row within region
        int c = i & 7;                         // 16B unit
        const __half* src = ((j < 4) ? A : B) + r * K + k0 + c * 8;
        uint32_t dst = so + ((j < 4) ? 0u : (uint32_t)OFF_B)
                     + (uint32_t)r * 128 + (uint32_t)((c ^ (r & 7)) << 4);
        cp16(dst, src);
    }
}

__device__ __forceinline__ void compute_chunk(
    uint32_t so, int wm, int wn, int lane, float acc[4][4][4])
{
    const int ra = wm + (lane & 15);
    const int rb = wn + ((lane >> 4) << 3) + (lane & 7);
    const uint32_t a_row = so + (uint32_t)ra * 128;
    const uint32_t b_row = so + OFF_B + (uint32_t)rb * 128;
    const int ua = (lane >> 4);
    const int ub = ((lane >> 3) & 1);

    #pragma unroll
    for (int ks = 0; ks < 4; ks++) {
        const uint32_t a_sw = (uint32_t)(((2 * ks + ua) ^ (ra & 7)) << 4);
        const uint32_t b_sw = (uint32_t)(((2 * ks + ub) ^ (rb & 7)) << 4);
        uint32_t A0[4], A1[4], A2[4], A3[4], B0[4], B1[4];
        LDSM4(A0, a_row + a_sw);
        LDSM4(A1, a_row + a_sw + 16 * 128);
        LDSM4(A2, a_row + a_sw + 32 * 128);
        LDSM4(A3, a_row + a_sw + 48 * 128);
        LDSM4(B0, b_row + b_sw);
        LDSM4(B1, b_row + b_sw + 16 * 128);
        MMA16816(acc[0][0], A0, B0);  MMA16816(acc[0][1], A0, B0 + 2);
        MMA16816(acc[0][2], A0, B1);  MMA16816(acc[0][3], A0, B1 + 2);
        MMA16816(acc[1][0], A1, B0);  MMA16816(acc[1][1], A1, B0 + 2);
        MMA16816(acc[1][2], A1, B1);  MMA16816(acc[1][3], A1, B1 + 2);
        MMA16816(acc[2][0], A2, B0);  MMA16816(acc[2][1], A2, B0 + 2);
        MMA16816(acc[2][2], A2, B1);  MMA16816(acc[2][3], A2, B1 + 2);
        MMA16816(acc[3][0], A3, B0);  MMA16816(acc[3][1], A3, B0 + 2);
        MMA16816(acc[3][2], A3, B1);  MMA16816(acc[3][3], A3, B1 + 2);
    }
}

template<int EPI>
__global__ void __launch_bounds__(256, 2) gemm_mma(
    const __half* __restrict__ A, const __half* __restrict__ B,
    int K, size_t Az, size_t Bz,
    __half* __restrict__ O0, __half* __restrict__ O1, __half* __restrict__ O2,
    float* __restrict__ Ofp,
    const float* __restrict__ b0, const float* __restrict__ b1,
    const float* __restrict__ b2,
    const float* __restrict__ resid, float scale)
{
    extern __shared__ __align__(16) uint8_t gsm[];
    const uint32_t sbase = smem_u32(gsm);
    const int tid = threadIdx.x, lane = tid & 31, wid = tid >> 5;
    const int wm = (wid >> 2) * 64, wn = (wid & 3) * 32;
    const int bz = blockIdx.z;
    const int m0 = blockIdx.y * 128, n0 = blockIdx.x * 128;

    const __half* Ap = A + (size_t)bz * Az + (size_t)m0 * K;
    const __half* Bp = B + (size_t)bz * Bz + (size_t)n0 * K;

    const int NT = K / 64;
    float acc[4][4][4] = {};

    load_stage(sbase + 0 * STAGE, Ap, Bp, K, 0, tid);  CP_COMMIT();
    load_stage(sbase + 1 * STAGE, Ap, Bp, K, 64, tid); CP_COMMIT();

    int s2 = 2, s0 = 0;
    for (int t = 0; t < NT; t++) {
        if (t + 1 < NT) {
            asm volatile("cp.async.wait_group 1;" ::: "memory");
        } else {
            asm volatile("cp.async.wait_group 0;" ::: "memory");
        }
        __syncthreads();
        if (t + 2 < NT) {
            load_stage(sbase + (uint32_t)s2 * STAGE, Ap, Bp, K, (t + 2) * 64, tid);
            CP_COMMIT();
        }
        compute_chunk(sbase + (uint32_t)s0 * STAGE, wm, wn, lane, acc);
        s0++; if (s0 == 3) s0 = 0;
        s2++; if (s2 == 3) s2 = 0;
    }
    __syncthreads();

    // -------- epilogue: single pass through 128x129 fp32 smem --------
    float* Sf = (float*)gsm;
    const int grp = lane >> 2, tg = lane & 3;
    #pragma unroll
    for (int mt = 0; mt < 4; mt++) {
        #pragma unroll
        for (int nf = 0; nf < 4; nf++) {
            int m = wm + mt * 16 + grp;
            int n = wn + nf * 8 + tg * 2;
            Sf[m * 129 + n]           = acc[mt][nf][0];
            Sf[m * 129 + n + 1]       = acc[mt][nf][1];
            Sf[(m + 8) * 129 + n]     = acc[mt][nf][2];
            Sf[(m + 8) * 129 + n + 1] = acc[mt][nf][3];
        }
    }
    __syncthreads();

    const int rr = tid >> 5;        // 0..7
    const int cc = tid & 31;        // 0..31
    const int wtype = m0 >> 9;      // QKV: 0=q,1=k,2=v
    const int mloc0 = m0 & (CH - 1);

    #pragma unroll 1
    for (int it = 0; it < 16; it++) {
        const int r = rr + it * 8;
        if (EPI == EPI_S) {
            const float* s = &Sf[r * 129 + cc * 4];
            size_t a = ((size_t)bz * NPIX + m0 + r) * NPIX + n0 + cc * 4;
            *(__half2*)&O0[a]     = h2(s[0], s[1]);
            *(__half2*)&O0[a + 2] = h2(s[2], s[3]);
        } else if (EPI == EPI_P) {
            const float bv = b0[m0 + r];
            size_t a = ((size_t)((n0 >> 12) * CH + m0 + r)) * NPIX
                     + (n0 & (NPIX - 1)) + cc * 4;
            float4 rd = *(const float4*)&resid[a];
            const float* s = &Sf[r * 129 + cc * 4];
            float4 o = make_float4(s[0] + bv + rd.x, s[1] + bv + rd.y,
                                   s[2] + bv + rd.z, s[3] + bv + rd.w);
            *(float4*)&Ofp[a] = o;
        } else if (EPI == EPI_AV) {
            size_t a = ((size_t)bz * NPIX + m0 + r) * CH + n0 + cc * 4;
            const float* s = &Sf[r * 129 + cc * 4];
            *(__half2*)&O0[a]     = h2(s[0], s[1]);
            *(__half2*)&O0[a + 2] = h2(s[2], s[3]);
        } else {    // EPI_QKV
            if (wtype == 2) {
                const float bv = b2[mloc0 + r];
                size_t a = ((size_t)((n0 >> 12) * CH + mloc0 + r)) * NPIX
                         + (n0 & (NPIX - 1)) + cc * 4;
                const float* s = &Sf[r * 129 + cc * 4];
                *(__half2*)&O2[a]     = h2(s[0] + bv, s[1] + bv);
                *(__half2*)&O2[a + 2] = h2(s[2] + bv, s[3] + bv);
            } else {
                __half* Op = (wtype == 0) ? O0 : O1;
                const float* bp = (wtype == 0) ? b0 : b1;
                const float sc = (wtype == 0) ? scale : 1.0f;
                size_t a = ((size_t)n0 + r) * CH + mloc0 + cc * 4;
                float v0 = (Sf[(cc * 4 + 0) * 129 + r] + bp[mloc0 + cc * 4 + 0]) * sc;
                float v1 = (Sf[(cc * 4 + 1) * 129 + r] + bp[mloc0 + cc * 4 + 1]) * sc;
                float v2 = (Sf[(cc * 4 + 2) * 129 + r] + bp[mloc0 + cc * 4 + 2]) * sc;
                float v3 = (Sf[(cc * 4 + 3) * 129 + r] + bp[mloc0 + cc * 4 + 3]) * sc;
                *(__half2*)&Op[a]     = h2(v0, v1);
                *(__half2*)&Op[a + 2] = h2(v2, v3);
            }
        }
    }
}

// -------------- softmax rows of fp16 scores -> attn fp16 --------------
__global__ void __launch_bounds__(256) softmax_kernel()
{
    const size_t row = blockIdx.x;       // 0 .. NFOLD-1
    const uint4* p = (const uint4*)(g_s + row * NPIX);   // 512 uint4 (8 halves each)
    uint4* oh = (uint4*)(g_at + row * NPIX);
    const int t = threadIdx.x;
    const int lane = t & 31, wid = t >> 5;

    float v[16];
    float mx = -1e30f;
    #pragma unroll
    for (int j = 0; j < 2; j++) {
        uint4 u = p[t + 256 * j];
        const uint32_t* q = (const uint32_t*)&u;
        #pragma unroll
        for (int w = 0; w < 4; w++) {
            float2 f = __half22float2(*(const __half2*)&q[w]);
            v[j * 8 + w * 2 + 0] = f.x;
            v[j * 8 + w * 2 + 1] = f.y;
            mx = fmaxf(mx, fmaxf(f.x, f.y));
        }
    }
    __shared__ float red[8];
    __shared__ float s_mx, s_sum;
    #pragma unroll
    for (int o = 16; o; o >>= 1) mx = fmaxf(mx, __shfl_xor_sync(0xffffffffu, mx, o));
    if (lane == 0) red[wid] = mx;
    __syncthreads();
    if (t == 0) {
        float m = red[0];
        #pragma unroll
        for (int i = 1; i < 8; i++) m = fmaxf(m, red[i]);
        s_mx = m;
    }
    __syncthreads();
    mx = s_mx;

    float sum = 0.f;
    #pragma unroll
    for (int i = 0; i < 16; i++) {
        v[i] = __expf(v[i] - mx);
        sum += v[i];
    }
    #pragma unroll
    for (int o = 16; o; o >>= 1) sum += __shfl_xor_sync(0xffffffffu, sum, o);
    if (lane == 0) red[wid] = sum;
    __syncthreads();
    if (t == 0) {
        float s = 0.f;
        #pragma unroll
        for (int i = 0; i < 8; i++) s += red[i];
        s_sum = s;
    }
    __syncthreads();
    const float inv = 1.0f / s_sum;

    #pragma unroll
    for (int j = 0; j < 2; j++) {
        uint4 u;
        uint32_t* q = (uint32_t*)&u;
        #pragma unroll
        for (int w = 0; w < 4; w++) {
            __half2 hh = h2(v[j * 8 + w * 2] * inv, v[j * 8 + w * 2 + 1] * inv);
            q[w] = *(uint32_t*)&hh;
        }
        oh[t + 256 * j] = u;
    }
}

// ------------------------- launcher -------------------------
extern "C" void kernel_launch(void* const* d_in, const int* in_sizes, int n_in,
                              void* d_out, int out_size)
{
    const float* x     = (const float*)d_in[0];
    const float* gamma = (const float*)d_in[1];
    const float* beta  = (const float*)d_in[2];
    const float* Wq    = (const float*)d_in[3];
    const float* bq    = (const float*)d_in[4];
    const float* Wk    = (const float*)d_in[5];
    const float* bk    = (const float*)d_in[6];
    const float* Wv    = (const float*)d_in[7];
    const float* bv    = (const float*)d_in[8];
    const float* Wo    = (const float*)d_in[9];
    const float* bo    = (const float*)d_in[10];
    float* out = (float*)d_out;

    void* p;
    __half *w, *hnT, *qT, *kT, *v, *at, *oT, *sh;
    cudaGetSymbolAddress(&p, g_w);    w   = (__half*)p;
    cudaGetSymbolAddress(&p, g_hnT);  hnT = (__half*)p;
    cudaGetSymbolAddress(&p, g_qT);   qT  = (__half*)p;
    cudaGetSymbolAddress(&p, g_kT);   kT  = (__half*)p;
    cudaGetSymbolAddress(&p, g_v);    v   = (__half*)p;
    cudaGetSymbolAddress(&p, g_at);   at  = (__half*)p;
    cudaGetSymbolAddress(&p, g_oT);   oT  = (__half*)p;
    cudaGetSymbolAddress(&p, g_s);    sh  = (__half*)p;

    cudaFuncSetAttribute(gemm_mma<EPI_QKV>, cudaFuncAttributeMaxDynamicSharedMemorySize, SMEM_GEMM);
    cudaFuncSetAttribute(gemm_mma<EPI_S>,   cudaFuncAttributeMaxDynamicSharedMemorySize, SMEM_GEMM);
    cudaFuncSetAttribute(gemm_mma<EPI_AV>,  cudaFuncAttributeMaxDynamicSharedMemorySize, SMEM_GEMM);
    cudaFuncSetAttribute(gemm_mma<EPI_P>,   cudaFuncAttributeMaxDynamicSharedMemorySize, SMEM_GEMM);

    const float scale = 1.0f / sqrtf((float)CH);
    const size_t WN = (size_t)CH * CH;

    // weights fp32 -> fp16 (stacked q,k,v,o)
    convert_w4_kernel<<<dim3(WN / 4 / 256, 4), 256>>>(Wq, Wk, Wv, Wo);
    // GroupNorm + transpose -> hnT
    gn_stats_kernel<<<dim3(32, BATCH), 256>>>(x);
    tnc_kernel<<<dim3(NPIX / 32, CH / 32, BATCH), 256>>>(x, gamma, beta);

    // fused QKV GEMM: A = stacked W [1536, 512], B = hnT [NFOLD, 512]
    dim3 gQKV(NFOLD / 128, 3 * CH / 128, 1);     // 64 x 12 = 768 CTAs
    gemm_mma<EPI_QKV><<<gQKV, 256, SMEM_GEMM>>>(
        w, hnT, CH, 0, 0,
        qT, kT, v, nullptr, bq, bk, bv, nullptr, scale);

    // scores (scale folded into q) -> fp16
    dim3 gS(NPIX / 128, NPIX / 128, BATCH);      // 32 x 32 x 2 = 2048 CTAs
    gemm_mma<EPI_S><<<gS, 256, SMEM_GEMM>>>(
        qT, kT, CH, (size_t)NPIX * CH, (size_t)NPIX * CH,
        sh, nullptr, nullptr, nullptr, nullptr, nullptr, nullptr, nullptr, 0.f);

    // softmax -> attn fp16
    softmax_kernel<<<NFOLD, 256>>>();

    // AV: D[i,c] = sum_j attn[i,j] v[c,j] -> oT row-major [NFOLD, CH]
    dim3 gAV(CH / 128, NPIX / 128, BATCH);       // 4 x 32 x 2 = 256 CTAs
    gemm_mma<EPI_AV><<<gAV, 256, SMEM_GEMM>>>(
        at, v, NPIX, (size_t)NPIX * NPIX, (size_t)CH * NPIX,
        oT, nullptr, nullptr, nullptr, nullptr, nullptr, nullptr, nullptr, 0.f);

    // proj + bias + residual -> out
    dim3 gP(NFOLD / 128, CH / 128, 1);           // 64 x 4 = 256 CTAs
    gemm_mma<EPI_P><<<gP, 256, SMEM_GEMM>>>(
        w + 3 * WN, oT, CH, 0, 0,
        nullptr, nullptr, nullptr, out, bo, nullptr, nullptr, x, 0.f);

    (void)in_sizes; (void)n_in; (void)out_size;
}

// round 15
// speedup vs baseline: 1.3098x; 1.1140x over previous
#include <cuda_runtime.h>
#include <cuda_fp16.h>
#include <cstdint>
#include <cmath>

#define BATCH 2
#define CH    512
#define NPIX  4096
#define NFOLD (BATCH * NPIX)     // 8192
#define EPS   1e-6f

// ------------------------- scratch (device globals) -------------------------
static __device__ float2 g_stats[BATCH * 32];
static __device__ __half g_w[4 * CH * CH];                     // q,k,v,o stacked
static __device__ __half g_hnT[(size_t)NFOLD * CH];
static __device__ __half g_qT[(size_t)NFOLD * CH];
static __device__ __half g_kT[(size_t)NFOLD * CH];
static __device__ __half g_v[(size_t)BATCH * CH * NPIX];
static __device__ __half g_s[(size_t)BATCH * NPIX * NPIX];     // fp16 scores, 67 MB
static __device__ __half g_at[(size_t)BATCH * NPIX * NPIX];    // 67 MB
static __device__ __half g_oT[(size_t)NFOLD * CH];

// ------------------------- small helpers -------------------------
__device__ __forceinline__ void cp16(uint32_t s, const void* g) {
    asm volatile("cp.async.cg.shared.global [%0], [%1], 16;" :: "r"(s), "l"(g));
}

#define CP_COMMIT() asm volatile("cp.async.commit_group;" ::: "memory")

#define LDSM4(R, addr) \
    asm volatile("ldmatrix.sync.aligned.m8n8.x4.shared.b16 {%0,%1,%2,%3}, [%4];" \
        : "=r"((R)[0]), "=r"((R)[1]), "=r"((R)[2]), "=r"((R)[3]) : "r"(addr))

#define MMA16816(D, A, B) \
    asm volatile("mma.sync.aligned.m16n8k16.row.col.f32.f16.f16.f32 " \
        "{%0,%1,%2,%3}, {%4,%5,%6,%7}, {%8,%9}, {%0,%1,%2,%3};" \
        : "+f"((D)[0]), "+f"((D)[1]), "+f"((D)[2]), "+f"((D)[3]) \
        : "r"((A)[0]), "r"((A)[1]), "r"((A)[2]), "r"((A)[3]), \
          "r"((B)[0]), "r"((B)[1]))

__device__ __forceinline__ uint32_t smem_u32(const void* p) {
    uint32_t a;
    asm("{ .reg .u64 t; cvta.to.shared.u64 t, %1; cvt.u32.u64 %0, t; }"
        : "=r"(a) : "l"(p));
    return a;
}

__device__ __forceinline__ __half2 h2(float a, float b) {
    return __halves2half2(__float2half_rn(a), __float2half_rn(b));
}

// ---------- merged preproc: W fp32->fp16 (blocks 0..1023) + GroupNorm stats (1024..1087) ----------
__global__ void __launch_bounds__(256) preproc_kernel(
    const float* __restrict__ w0, const float* __restrict__ w1,
    const float* __restrict__ w2, const float* __restrict__ w3,
    const float* __restrict__ x)
{
    if (blockIdx.x < 1024) {
        const int wsel = blockIdx.x >> 8;
        const float* src = (wsel == 0) ? w0 : (wsel == 1) ? w1
                         : (wsel == 2) ? w2 : w3;
        int i = (blockIdx.x & 255) * 256 + threadIdx.x;
        float4 v = ((const float4*)src)[i];
        size_t e = (size_t)wsel * CH * CH + (size_t)i * 4;
        __half2* d = (__half2*)(g_w + e);
        d[0] = h2(v.x, v.y);
        d[1] = h2(v.z, v.w);
        return;
    }
    // GroupNorm stats
    const int bi = blockIdx.x - 1024;
    const int g = bi & 31, b = bi >> 5;
    const size_t base = ((size_t)b * CH + (size_t)g * 16) * NPIX;
    const float4* x4 = (const float4*)(x + base);
    const int n4 = 16 * NPIX / 4;

    float s = 0.f, ss = 0.f;
    for (int i = threadIdx.x; i < n4; i += 256) {
        float4 v = x4[i];
        s  += v.x + v.y + v.z + v.w;
        ss += v.x * v.x + v.y * v.y + v.z * v.z + v.w * v.w;
    }
    __shared__ float rs[8], rss[8];
    #pragma unroll
    for (int o = 16; o; o >>= 1) {
        s  += __shfl_xor_sync(0xffffffffu, s, o);
        ss += __shfl_xor_sync(0xffffffffu, ss, o);
    }
    const int lane = threadIdx.x & 31, wid = threadIdx.x >> 5;
    if (lane == 0) { rs[wid] = s; rss[wid] = ss; }
    __syncthreads();
    if (threadIdx.x == 0) {
        float ts = 0.f, tss = 0.f;
        #pragma unroll
        for (int i = 0; i < 8; i++) { ts += rs[i]; tss += rss[i]; }
        const float inv_n = 1.0f / (16 * NPIX);
        float mean = ts * inv_n;
        float var = tss * inv_n - mean * mean;
        g_stats[b * 32 + g] = make_float2(mean, rsqrtf(var + EPS));
    }
}

// ---------- transpose + normalize + fp16 convert:  x[b,c,n] -> hnT[b*N+n, c] ----------
__global__ void __launch_bounds__(256) tnc_kernel(
    const float* __restrict__ x, const float* __restrict__ gamma,
    const float* __restrict__ beta)
{
    __shared__ float tile[32][33];
    const int b = blockIdx.z;
    const int n0 = blockIdx.x * 32, c0 = blockIdx.y * 32;
    const int tx = threadIdx.x & 31, ty = threadIdx.x >> 5;   // 32 x 8

    #pragma unroll
    for (int j = 0; j < 4; j++) {
        int c = c0 + ty + j * 8;
        float2 st = g_stats[b * 32 + (c >> 4)];
        float gm = gamma[c] * st.y;
        float bt = beta[c] - st.x * gm;
        float v = x[((size_t)(b * CH + c)) * NPIX + n0 + tx];
        tile[ty + j * 8][tx] = v * gm + bt;
    }
    __syncthreads();
    #pragma unroll
    for (int j = 0; j < 4; j++) {
        int n = n0 + ty + j * 8;
        float v = tile[tx][ty + j * 8];
        size_t a = ((size_t)(b * NPIX + n)) * CH + c0 + tx;
        g_hnT[a] = __float2half_rn(v);
    }
}

// ------------------------- mma.sync GEMM (fp16, 8 warps, 64x32 warp tile) -------------------------
// D[m,n] = sum_k A[m,k]*B[n,k], K-major fp16, fp32 acc.
// CTA: 128(M) x 128(N), K-chunk 64, XOR-swizzled 128B rows, 3-stage cp.async.
// 256 thr = 8 warps in 2(M) x 4(N); warp tile 64x32. __launch_bounds__(256,2).
#define OFF_B    16384
#define STAGE    32768
#define SMEM_GEMM (3 * STAGE)    // 98304

enum { EPI_QKV = 0, EPI_S = 1, EPI_AV = 2, EPI_P = 3 };

__device__ __forceinline__ void load_stage(
    uint32_t so, const __half* __restrict__ A, const __half* __restrict__ B,
    int K, int k0, int tid)
{
    #pragma unroll
    for (int j = 0; j < 8; j++) {
        int i = tid + j * 256;                 // 0..2047
        int r = (i >> 3) & 127;                // row within region
        int c = i & 7;                         // 16B unit
        const __half* src = ((j < 4) ? A : B) + r * K + k0 + c * 8;
        uint32_t dst = so + ((j < 4) ? 0u : (uint32_t)OFF_B)
                     + (uint32_t)r * 128 + (uint32_t)((c ^ (r & 7)) << 4);
        cp16(dst, src);
    }
}

__device__ __forceinline__ void compute_chunk(
    uint32_t so, int wm, int wn, int lane, float acc[4][4][4])
{
    const int ra = wm + (lane & 15);
    const int rb = wn + ((lane >> 4) << 3) + (lane & 7);
    const uint32_t a_row = so + (uint32_t)ra * 128;
    const uint32_t b_row = so + OFF_B + (uint32_t)rb * 128;
    const int ua = (lane >> 4);
    const int ub = ((lane >> 3) & 1);

    #pragma unroll
    for (int ks = 0; ks < 4; ks++) {
        const uint32_t a_sw = (uint32_t)(((2 * ks + ua) ^ (ra & 7)) << 4);
        const uint32_t b_sw = (uint32_t)(((2 * ks + ub) ^ (rb & 7)) << 4);
        uint32_t A0[4], A1[4], A2[4], A3[4], B0[4], B1[4];
        LDSM4(A0, a_row + a_sw);
        LDSM4(A1, a_row + a_sw + 16 * 128);
        LDSM4(A2, a_row + a_sw + 32 * 128);
        LDSM4(A3, a_row + a_sw + 48 * 128);
        LDSM4(B0, b_row + b_sw);
        LDSM4(B1, b_row + b_sw + 16 * 128);
        MMA16816(acc[0][0], A0, B0);  MMA16816(acc[0][1], A0, B0 + 2);
        MMA16816(acc[0][2], A0, B1);  MMA16816(acc[0][3], A0, B1 + 2);
        MMA16816(acc[1][0], A1, B0);  MMA16816(acc[1][1], A1, B0 + 2);
        MMA16816(acc[1][2], A1, B1);  MMA16816(acc[1][3], A1, B1 + 2);
        MMA16816(acc[2][0], A2, B0);  MMA16816(acc[2][1], A2, B0 + 2);
        MMA16816(acc[2][2], A2, B1);  MMA16816(acc[2][3], A2, B1 + 2);
        MMA16816(acc[3][0], A3, B0);  MMA16816(acc[3][1], A3, B0 + 2);
        MMA16816(acc[3][2], A3, B1);  MMA16816(acc[3][3], A3, B1 + 2);
    }
}

template<int EPI>
__global__ void __launch_bounds__(256, 2) gemm_mma(
    const __half* __restrict__ A, const __half* __restrict__ B,
    int K, size_t Az, size_t Bz,
    __half* __restrict__ O0, __half* __restrict__ O1, __half* __restrict__ O2,
    float* __restrict__ Ofp,
    const float* __restrict__ b0, const float* __restrict__ b1,
    const float* __restrict__ b2,
    const float* __restrict__ resid, float scale)
{
    extern __shared__ __align__(16) uint8_t gsm[];
    const uint32_t sbase = smem_u32(gsm);
    const int tid = threadIdx.x, lane = tid & 31, wid = tid >> 5;
    const int wm = (wid >> 2) * 64, wn = (wid & 3) * 32;
    const int bz = blockIdx.z;
    const int m0 = blockIdx.y * 128, n0 = blockIdx.x * 128;

    const __half* Ap = A + (size_t)bz * Az + (size_t)m0 * K;
    const __half* Bp = B + (size_t)bz * Bz + (size_t)n0 * K;

    const int NT = K / 64;
    float acc[4][4][4] = {};

    load_stage(sbase + 0 * STAGE, Ap, Bp, K, 0, tid);  CP_COMMIT();
    load_stage(sbase + 1 * STAGE, Ap, Bp, K, 64, tid); CP_COMMIT();

    int s2 = 2, s0 = 0;
    for (int t = 0; t < NT; t++) {
        if (t + 1 < NT) {
            asm volatile("cp.async.wait_group 1;" ::: "memory");
        } else {
            asm volatile("cp.async.wait_group 0;" ::: "memory");
        }
        __syncthreads();
        if (t + 2 < NT) {
            load_stage(sbase + (uint32_t)s2 * STAGE, Ap, Bp, K, (t + 2) * 64, tid);
            CP_COMMIT();
        }
        compute_chunk(sbase + (uint32_t)s0 * STAGE, wm, wn, lane, acc);
        s0++; if (s0 == 3) s0 = 0;
        s2++; if (s2 == 3) s2 = 0;
    }
    __syncthreads();

    const int grp = lane >> 2, tg = lane & 3;
    const int rr = tid >> 5;        // 0..7
    const int cc = tid & 31;        // 0..31

    if (EPI == EPI_S || EPI == EPI_AV) {
        // fp16 staging, 256B pitch, XOR-swizzled within row: phys = n*2 ^ ((m&7)<<4).
        // Write banks tg + 4*(nf^grp): all distinct. Read uint2 at cc*8 ^ ((r&7)<<4)
        // retrieves logical cols cc*4..cc*4+3 (XOR bits 4-6 don't cross the 8B granule).
        #pragma unroll
        for (int mt = 0; mt < 4; mt++) {
            #pragma unroll
            for (int nf = 0; nf < 4; nf++) {
                int m = wm + mt * 16 + grp;
                int n = wn + nf * 8 + tg * 2;
                uint32_t sw = (uint32_t)((m & 7) << 4);      // (m+8)&7 == m&7
                uint32_t off = (uint32_t)(n * 2) ^ sw;
                *(__half2*)(gsm + (uint32_t)m * 256 + off) =
                    h2(acc[mt][nf][0], acc[mt][nf][1]);
                *(__half2*)(gsm + (uint32_t)(m + 8) * 256 + off) =
                    h2(acc[mt][nf][2], acc[mt][nf][3]);
            }
        }
        __syncthreads();
        #pragma unroll 1
        for (int it = 0; it < 16; it++) {
            const int r = rr + it * 8;
            uint32_t off = (uint32_t)(cc * 8) ^ (uint32_t)((r & 7) << 4);
            uint2 u = *(const uint2*)(gsm + (uint32_t)r * 256 + off);
            if (EPI == EPI_S) {
                size_t a = ((size_t)bz * NPIX + m0 + r) * NPIX + n0 + cc * 4;
                *(uint2*)&O0[a] = u;
            } else {
                size_t a = ((size_t)bz * NPIX + m0 + r) * CH + n0 + cc * 4;
                *(uint2*)&O0[a] = u;
            }
        }
        return;
    }

    // -------- fp32 staging path (EPI_QKV / EPI_P) --------
    float* Sf = (float*)gsm;
    #pragma unroll
    for (int mt = 0; mt < 4; mt++) {
        #pragma unroll
        for (int nf = 0; nf < 4; nf++) {
            int m = wm + mt * 16 + grp;
            int n = wn + nf * 8 + tg * 2;
            Sf[m * 129 + n]           = acc[mt][nf][0];
            Sf[m * 129 + n + 1]       = acc[mt][nf][1];
            Sf[(m + 8) * 129 + n]     = acc[mt][nf][2];
            Sf[(m + 8) * 129 + n + 1] = acc[mt][nf][3];
        }
    }
    __syncthreads();

    const int wtype = m0 >> 9;      // QKV: 0=q,1=k,2=v
    const int mloc0 = m0 & (CH - 1);

    #pragma unroll 1
    for (int it = 0; it < 16; it++) {
        const int r = rr + it * 8;
        if (EPI == EPI_P) {
            const float bv = b0[m0 + r];
            size_t a = ((size_t)((n0 >> 12) * CH + m0 + r)) * NPIX
                     + (n0 & (NPIX - 1)) + cc * 4;
            float4 rd = *(const float4*)&resid[a];
            const float* s = &Sf[r * 129 + cc * 4];
            float4 o = make_float4(s[0] + bv + rd.x, s[1] + bv + rd.y,
                                   s[2] + bv + rd.z, s[3] + bv + rd.w);
            *(float4*)&Ofp[a] = o;
        } else {    // EPI_QKV
            if (wtype == 2) {
                const float bv = b2[mloc0 + r];
                size_t a = ((size_t)((n0 >> 12) * CH + mloc0 + r)) * NPIX
                         + (n0 & (NPIX - 1)) + cc * 4;
                const float* s = &Sf[r * 129 + cc * 4];
                *(__half2*)&O2[a]     = h2(s[0] + bv, s[1] + bv);
                *(__half2*)&O2[a + 2] = h2(s[2] + bv, s[3] + bv);
            } else {
                __half* Op = (wtype == 0) ? O0 : O1;
                const float* bp = (wtype == 0) ? b0 : b1;
                const float sc = (wtype == 0) ? scale : 1.0f;
                size_t a = ((size_t)n0 + r) * CH + mloc0 + cc * 4;
                float v0 = (Sf[(cc * 4 + 0) * 129 + r] + bp[mloc0 + cc * 4 + 0]) * sc;
                float v1 = (Sf[(cc * 4 + 1) * 129 + r] + bp[mloc0 + cc * 4 + 1]) * sc;
                float v2 = (Sf[(cc * 4 + 2) * 129 + r] + bp[mloc0 + cc * 4 + 2]) * sc;
                float v3 = (Sf[(cc * 4 + 3) * 129 + r] + bp[mloc0 + cc * 4 + 3]) * sc;
                *(__half2*)&Op[a]     = h2(v0, v1);
                *(__half2*)&Op[a + 2] = h2(v2, v3);
            }
        }
    }
}

// -------------- softmax rows of fp16 scores -> attn fp16 --------------
__global__ void __launch_bounds__(256) softmax_kernel()
{
    const size_t row = blockIdx.x;       // 0 .. NFOLD-1
    const uint4* p = (const uint4*)(g_s + row * NPIX);   // 512 uint4 (8 halves each)
    uint4* oh = (uint4*)(g_at + row * NPIX);
    const int t = threadIdx.x;
    const int lane = t & 31, wid = t >> 5;

    float v[16];
    float mx = -1e30f;
    #pragma unroll
    for (int j = 0; j < 2; j++) {
        uint4 u = p[t + 256 * j];
        const uint32_t* q = (const uint32_t*)&u;
        #pragma unroll
        for (int w = 0; w < 4; w++) {
            float2 f = __half22float2(*(const __half2*)&q[w]);
            v[j * 8 + w * 2 + 0] = f.x;
            v[j * 8 + w * 2 + 1] = f.y;
            mx = fmaxf(mx, fmaxf(f.x, f.y));
        }
    }
    __shared__ float red[8];
    __shared__ float s_mx, s_sum;
    #pragma unroll
    for (int o = 16; o; o >>= 1) mx = fmaxf(mx, __shfl_xor_sync(0xffffffffu, mx, o));
    if (lane == 0) red[wid] = mx;
    __syncthreads();
    if (t == 0) {
        float m = red[0];
        #pragma unroll
        for (int i = 1; i < 8; i++) m = fmaxf(m, red[i]);
        s_mx = m;
    }
    __syncthreads();
    mx = s_mx;

    float sum = 0.f;
    #pragma unroll
    for (int i = 0; i < 16; i++) {
        v[i] = __expf(v[i] - mx);
        sum += v[i];
    }
    #pragma unroll
    for (int o = 16; o; o >>= 1) sum += __shfl_xor_sync(0xffffffffu, sum, o);
    if (lane == 0) red[wid] = sum;
    __syncthreads();
    if (t == 0) {
        float s = 0.f;
        #pragma unroll
        for (int i = 0; i < 8; i++) s += red[i];
        s_sum = s;
    }
    __syncthreads();
    const float inv = 1.0f / s_sum;

    #pragma unroll
    for (int j = 0; j < 2; j++) {
        uint4 u;
        uint32_t* q = (uint32_t*)&u;
        #pragma unroll
        for (int w = 0; w < 4; w++) {
            __half2 hh = h2(v[j * 8 + w * 2] * inv, v[j * 8 + w * 2 + 1] * inv);
            q[w] = *(uint32_t*)&hh;
        }
        oh[t + 256 * j] = u;
    }
}

// ------------------------- launcher -------------------------
extern "C" void kernel_launch(void* const* d_in, const int* in_sizes, int n_in,
                              void* d_out, int out_size)
{
    const float* x     = (const float*)d_in[0];
    const float* gamma = (const float*)d_in[1];
    const float* beta  = (const float*)d_in[2];
    const float* Wq    = (const float*)d_in[3];
    const float* bq    = (const float*)d_in[4];
    const float* Wk    = (const float*)d_in[5];
    const float* bk    = (const float*)d_in[6];
    const float* Wv    = (const float*)d_in[7];
    const float* bv    = (const float*)d_in[8];
    const float* Wo    = (const float*)d_in[9];
    const float* bo    = (const float*)d_in[10];
    float* out = (float*)d_out;

    void* p;
    __half *w, *hnT, *qT, *kT, *v, *at, *oT, *sh;
    cudaGetSymbolAddress(&p, g_w);    w   = (__half*)p;
    cudaGetSymbolAddress(&p, g_hnT);  hnT = (__half*)p;
    cudaGetSymbolAddress(&p, g_qT);   qT  = (__half*)p;
    cudaGetSymbolAddress(&p, g_kT);   kT  = (__half*)p;
    cudaGetSymbolAddress(&p, g_v);    v   = (__half*)p;
    cudaGetSymbolAddress(&p, g_at);   at  = (__half*)p;
    cudaGetSymbolAddress(&p, g_oT);   oT  = (__half*)p;
    cudaGetSymbolAddress(&p, g_s);    sh  = (__half*)p;

    cudaFuncSetAttribute(gemm_mma<EPI_QKV>, cudaFuncAttributeMaxDynamicSharedMemorySize, SMEM_GEMM);
    cudaFuncSetAttribute(gemm_mma<EPI_S>,   cudaFuncAttributeMaxDynamicSharedMemorySize, SMEM_GEMM);
    cudaFuncSetAttribute(gemm_mma<EPI_AV>,  cudaFuncAttributeMaxDynamicSharedMemorySize, SMEM_GEMM);
    cudaFuncSetAttribute(gemm_mma<EPI_P>,   cudaFuncAttributeMaxDynamicSharedMemorySize, SMEM_GEMM);

    const float scale = 1.0f / sqrtf((float)CH);
    const size_t WN = (size_t)CH * CH;

    // merged: weights fp32->fp16 (blocks 0..1023) + GroupNorm stats (1024..1087)
    preproc_kernel<<<1088, 256>>>(Wq, Wk, Wv, Wo, x);
    // transpose+normalize -> hnT
    tnc_kernel<<<dim3(NPIX / 32, CH / 32, BATCH), 256>>>(x, gamma, beta);

    // fused QKV GEMM: A = stacked W [1536, 512], B = hnT [NFOLD, 512]
    dim3 gQKV(NFOLD / 128, 3 * CH / 128, 1);     // 64 x 12 = 768 CTAs
    gemm_mma<EPI_QKV><<<gQKV, 256, SMEM_GEMM>>>(
        w, hnT, CH, 0, 0,
        qT, kT, v, nullptr, bq, bk, bv, nullptr, scale);

    // scores (scale folded into q) -> fp16
    dim3 gS(NPIX / 128, NPIX / 128, BATCH);      // 32 x 32 x 2 = 2048 CTAs
    gemm_mma<EPI_S><<<gS, 256, SMEM_GEMM>>>(
        qT, kT, CH, (size_t)NPIX * CH, (size_t)NPIX * CH,
        sh, nullptr, nullptr, nullptr, nullptr, nullptr, nullptr, nullptr, 0.f);

    // softmax -> attn fp16
    softmax_kernel<<<NFOLD, 256>>>();

    // AV: D[i,c] = sum_j attn[i,j] v[c,j] -> oT row-major [NFOLD, CH]
    dim3 gAV(CH / 128, NPIX / 128, BATCH);       // 4 x 32 x 2 = 256 CTAs
    gemm_mma<EPI_AV><<<gAV, 256, SMEM_GEMM>>>(
        at, v, NPIX, (size_t)NPIX * NPIX, (size_t)CH * NPIX,
        oT, nullptr, nullptr, nullptr, nullptr, nullptr, nullptr, nullptr, 0.f);

    // proj + bias + residual -> out
    dim3 gP(NFOLD / 128, CH / 128, 1);           // 64 x 4 = 256 CTAs
    gemm_mma<EPI_P><<<gP, 256, SMEM_GEMM>>>(
        w + 3 * WN, oT, CH, 0, 0,
        nullptr, nullptr, nullptr, out, bo, nullptr, nullptr, x, 0.f);

    (void)in_sizes; (void)n_in; (void)out_size;
}

// round 16
// speedup vs baseline: 1.3579x; 1.0367x over previous
#include <cuda_runtime.h>
#include <cuda_fp16.h>
#include <cstdint>
#include <cmath>

#define BATCH 2
#define CH    512
#define NPIX  4096
#define NFOLD (BATCH * NPIX)     // 8192
#define EPS   1e-6f

// ------------------------- scratch (device globals) -------------------------
static __device__ float2 g_stats[BATCH * 32];
static __device__ __half g_w[4 * CH * CH];                     // q,k,v,o stacked
static __device__ __half g_hnT[(size_t)NFOLD * CH];
static __device__ __half g_qT[(size_t)NFOLD * CH];
static __device__ __half g_kT[(size_t)NFOLD * CH];
static __device__ __half g_v[(size_t)BATCH * CH * NPIX];
static __device__ __half g_s[(size_t)BATCH * NPIX * NPIX];     // fp16 scores, 67 MB
static __device__ __half g_at[(size_t)BATCH * NPIX * NPIX];    // 67 MB
static __device__ __half g_oT[(size_t)NFOLD * CH];

// ------------------------- small helpers -------------------------
__device__ __forceinline__ void cp16(uint32_t s, const void* g) {
    asm volatile("cp.async.cg.shared.global [%0], [%1], 16;" :: "r"(s), "l"(g));
}

#define CP_COMMIT() asm volatile("cp.async.commit_group;" ::: "memory")

#define LDSM4(R, addr) \
    asm volatile("ldmatrix.sync.aligned.m8n8.x4.shared.b16 {%0,%1,%2,%3}, [%4];" \
        : "=r"((R)[0]), "=r"((R)[1]), "=r"((R)[2]), "=r"((R)[3]) : "r"(addr))

#define STMAT4T(addr, r0, r1, r2, r3) \
    asm volatile("stmatrix.sync.aligned.m8n8.x4.trans.shared.b16 [%0], {%1,%2,%3,%4};" \
        :: "r"(addr), "r"(r0), "r"(r1), "r"(r2), "r"(r3) : "memory")

#define MMA16816(D, A, B) \
    asm volatile("mma.sync.aligned.m16n8k16.row.col.f32.f16.f16.f32 " \
        "{%0,%1,%2,%3}, {%4,%5,%6,%7}, {%8,%9}, {%0,%1,%2,%3};" \
        : "+f"((D)[0]), "+f"((D)[1]), "+f"((D)[2]), "+f"((D)[3]) \
        : "r"((A)[0]), "r"((A)[1]), "r"((A)[2]), "r"((A)[3]), \
          "r"((B)[0]), "r"((B)[1]))

__device__ __forceinline__ uint32_t smem_u32(const void* p) {
    uint32_t a;
    asm("{ .reg .u64 t; cvta.to.shared.u64 t, %1; cvt.u32.u64 %0, t; }"
        : "=r"(a) : "l"(p));
    return a;
}

__device__ __forceinline__ __half2 h2(float a, float b) {
    return __halves2half2(__float2half_rn(a), __float2half_rn(b));
}

__device__ __forceinline__ uint32_t h2u(__half2 v) {
    return *(uint32_t*)&v;
}

// ---------- merged preproc: W fp32->fp16 (blocks 0..1023) + GroupNorm stats (1024..1087) ----------
__global__ void __launch_bounds__(256) preproc_kernel(
    const float* __restrict__ w0, const float* __restrict__ w1,
    const float* __restrict__ w2, const float* __restrict__ w3,
    const float* __restrict__ x)
{
    if (blockIdx.x < 1024) {
        const int wsel = blockIdx.x >> 8;
        const float* src = (wsel == 0) ? w0 : (wsel == 1) ? w1
                         : (wsel == 2) ? w2 : w3;
        int i = (blockIdx.x & 255) * 256 + threadIdx.x;
        float4 v = ((const float4*)src)[i];
        size_t e = (size_t)wsel * CH * CH + (size_t)i * 4;
        __half2* d = (__half2*)(g_w + e);
        d[0] = h2(v.x, v.y);
        d[1] = h2(v.z, v.w);
        return;
    }
    // GroupNorm stats
    const int bi = blockIdx.x - 1024;
    const int g = bi & 31, b = bi >> 5;
    const size_t base = ((size_t)b * CH + (size_t)g * 16) * NPIX;
    const float4* x4 = (const float4*)(x + base);
    const int n4 = 16 * NPIX / 4;

    float s = 0.f, ss = 0.f;
    for (int i = threadIdx.x; i < n4; i += 256) {
        float4 v = x4[i];
        s  += v.x + v.y + v.z + v.w;
        ss += v.x * v.x + v.y * v.y + v.z * v.z + v.w * v.w;
    }
    __shared__ float rs[8], rss[8];
    #pragma unroll
    for (int o = 16; o; o >>= 1) {
        s  += __shfl_xor_sync(0xffffffffu, s, o);
        ss += __shfl_xor_sync(0xffffffffu, ss, o);
    }
    const int lane = threadIdx.x & 31, wid = threadIdx.x >> 5;
    if (lane == 0) { rs[wid] = s; rss[wid] = ss; }
    __syncthreads();
    if (threadIdx.x == 0) {
        float ts = 0.f, tss = 0.f;
        #pragma unroll
        for (int i = 0; i < 8; i++) { ts += rs[i]; tss += rss[i]; }
        const float inv_n = 1.0f / (16 * NPIX);
        float mean = ts * inv_n;
        float var = tss * inv_n - mean * mean;
        g_stats[b * 32 + g] = make_float2(mean, rsqrtf(var + EPS));
    }
}

// ---------- transpose + normalize + fp16 convert:  x[b,c,n] -> hnT[b*N+n, c] ----------
__global__ void __launch_bounds__(256) tnc_kernel(
    const float* __restrict__ x, const float* __restrict__ gamma,
    const float* __restrict__ beta)
{
    __shared__ float tile[32][33];
    const int b = blockIdx.z;
    const int n0 = blockIdx.x * 32, c0 = blockIdx.y * 32;
    const int tx = threadIdx.x & 31, ty = threadIdx.x >> 5;   // 32 x 8

    #pragma unroll
    for (int j = 0; j < 4; j++) {
        int c = c0 + ty + j * 8;
        float2 st = g_stats[b * 32 + (c >> 4)];
        float gm = gamma[c] * st.y;
        float bt = beta[c] - st.x * gm;
        float v = x[((size_t)(b * CH + c)) * NPIX + n0 + tx];
        tile[ty + j * 8][tx] = v * gm + bt;
    }
    __syncthreads();
    #pragma unroll
    for (int j = 0; j < 4; j++) {
        int n = n0 + ty + j * 8;
        float v = tile[tx][ty + j * 8];
        size_t a = ((size_t)(b * NPIX + n)) * CH + c0 + tx;
        g_hnT[a] = __float2half_rn(v);
    }
}

// ------------------------- mma.sync GEMM (fp16, 8 warps, 64x32 warp tile) -------------------------
// D[m,n] = sum_k A[m,k]*B[n,k], K-major fp16, fp32 acc.
// CTA: 128(M) x 128(N), K-chunk 64, XOR-swizzled 128B rows, 3-stage cp.async.
// 256 thr = 8 warps in 2(M) x 4(N); warp tile 64x32. __launch_bounds__(256,2).
#define OFF_B    16384
#define STAGE    32768
#define SMEM_GEMM (3 * STAGE)    // 98304

enum { EPI_QKV = 0, EPI_S = 1, EPI_AV = 2, EPI_P = 3 };

__device__ __forceinline__ void load_stage(
    uint32_t so, const __half* __restrict__ A, const __half* __restrict__ B,
    int K, int k0, int tid)
{
    #pragma unroll
    for (int j = 0; j < 8; j++) {
        int i = tid + j * 256;                 // 0..2047
        int r = (i >> 3) & 127;                // row within region
        int c = i & 7;                         // 16B unit
        const __half* src = ((j < 4) ? A : B) + r * K + k0 + c * 8;
        uint32_t dst = so + ((j < 4) ? 0u : (uint32_t)OFF_B)
                     + (uint32_t)r * 128 + (uint32_t)((c ^ (r & 7)) << 4);
        cp16(dst, src);
    }
}

__device__ __forceinline__ void compute_chunk(
    uint32_t so, int wm, int wn, int lane, float acc[4][4][4])
{
    const int ra = wm + (lane & 15);
    const int rb = wn + ((lane >> 4) << 3) + (lane & 7);
    const uint32_t a_row = so + (uint32_t)ra * 128;
    const uint32_t b_row = so + OFF_B + (uint32_t)rb * 128;
    const int ua = (lane >> 4);
    const int ub = ((lane >> 3) & 1);

    #pragma unroll
    for (int ks = 0; ks < 4; ks++) {
        const uint32_t a_sw = (uint32_t)(((2 * ks + ua) ^ (ra & 7)) << 4);
        const uint32_t b_sw = (uint32_t)(((2 * ks + ub) ^ (rb & 7)) << 4);
        uint32_t A0[4], A1[4], A2[4], A3[4], B0[4], B1[4];
        LDSM4(A0, a_row + a_sw);
        LDSM4(A1, a_row + a_sw + 16 * 128);
        LDSM4(A2, a_row + a_sw + 32 * 128);
        LDSM4(A3, a_row + a_sw + 48 * 128);
        LDSM4(B0, b_row + b_sw);
        LDSM4(B1, b_row + b_sw + 16 * 128);
        MMA16816(acc[0][0], A0, B0);  MMA16816(acc[0][1], A0, B0 + 2);
        MMA16816(acc[0][2], A0, B1);  MMA16816(acc[0][3], A0, B1 + 2);
        MMA16816(acc[1][0], A1, B0);  MMA16816(acc[1][1], A1, B0 + 2);
        MMA16816(acc[1][2], A1, B1);  MMA16816(acc[1][3], A1, B1 + 2);
        MMA16816(acc[2][0], A2, B0);  MMA16816(acc[2][1], A2, B0 + 2);
        MMA16816(acc[2][2], A2, B1);  MMA16816(acc[2][3], A2, B1 + 2);
        MMA16816(acc[3][0], A3, B0);  MMA16816(acc[3][1], A3, B0 + 2);
        MMA16816(acc[3][2], A3, B1);  MMA16816(acc[3][3], A3, B1 + 2);
    }
}

template<int EPI>
__global__ void __launch_bounds__(256, 2) gemm_mma(
    const __half* __restrict__ A, const __half* __restrict__ B,
    int K, size_t Az, size_t Bz,
    __half* __restrict__ O0, __half* __restrict__ O1, __half* __restrict__ O2,
    float* __restrict__ Ofp,
    const float* __restrict__ b0, const float* __restrict__ b1,
    const float* __restrict__ b2,
    const float* __restrict__ resid, float scale)
{
    extern __shared__ __align__(16) uint8_t gsm[];
    const uint32_t sbase = smem_u32(gsm);
    const int tid = threadIdx.x, lane = tid & 31, wid = tid >> 5;
    const int wm = (wid >> 2) * 64, wn = (wid & 3) * 32;
    const int bz = blockIdx.z;
    const int m0 = blockIdx.y * 128, n0 = blockIdx.x * 128;

    const __half* Ap = A + (size_t)bz * Az + (size_t)m0 * K;
    const __half* Bp = B + (size_t)bz * Bz + (size_t)n0 * K;

    const int NT = K / 64;
    float acc[4][4][4] = {};

    load_stage(sbase + 0 * STAGE, Ap, Bp, K, 0, tid);  CP_COMMIT();
    load_stage(sbase + 1 * STAGE, Ap, Bp, K, 64, tid); CP_COMMIT();

    int s2 = 2, s0 = 0;
    for (int t = 0; t < NT; t++) {
        if (t + 1 < NT) {
            asm volatile("cp.async.wait_group 1;" ::: "memory");
        } else {
            asm volatile("cp.async.wait_group 0;" ::: "memory");
        }
        __syncthreads();
        if (t + 2 < NT) {
            load_stage(sbase + (uint32_t)s2 * STAGE, Ap, Bp, K, (t + 2) * 64, tid);
            CP_COMMIT();
        }
        compute_chunk(sbase + (uint32_t)s0 * STAGE, wm, wn, lane, acc);
        s0++; if (s0 == 3) s0 = 0;
        s2++; if (s2 == 3) s2 = 0;
    }
    __syncthreads();

    const int grp = lane >> 2, tg = lane & 3;
    const int rr = tid >> 5;        // 0..7
    const int cc = tid & 31;        // 0..31

    if (EPI == EPI_S || EPI == EPI_AV) {
        // fp16 staging, 256B pitch, XOR swizzle phys = n*2 ^ ((m&7)<<4)
        #pragma unroll
        for (int mt = 0; mt < 4; mt++) {
            #pragma unroll
            for (int nf = 0; nf < 4; nf++) {
                int m = wm + mt * 16 + grp;
                int n = wn + nf * 8 + tg * 2;
                uint32_t sw = (uint32_t)((m & 7) << 4);
                uint32_t off = (uint32_t)(n * 2) ^ sw;
                *(__half2*)(gsm + (uint32_t)m * 256 + off) =
                    h2(acc[mt][nf][0], acc[mt][nf][1]);
                *(__half2*)(gsm + (uint32_t)(m + 8) * 256 + off) =
                    h2(acc[mt][nf][2], acc[mt][nf][3]);
            }
        }
        __syncthreads();
        #pragma unroll 1
        for (int it = 0; it < 16; it++) {
            const int r = rr + it * 8;
            uint32_t off = (uint32_t)(cc * 8) ^ (uint32_t)((r & 7) << 4);
            uint2 u = *(const uint2*)(gsm + (uint32_t)r * 256 + off);
            if (EPI == EPI_S) {
                size_t a = ((size_t)bz * NPIX + m0 + r) * NPIX + n0 + cc * 4;
                *(uint2*)&O0[a] = u;
            } else {
                size_t a = ((size_t)bz * NPIX + m0 + r) * CH + n0 + cc * 4;
                *(uint2*)&O0[a] = u;
            }
        }
        return;
    }

    if (EPI == EPI_QKV) {
        const int wtype = m0 >> 9;      // 0=q,1=k,2=v
        const int mloc0 = m0 & (CH - 1);

        if (wtype == 2) {
            // ---- V: row-major fp16 staging with bias ----
            #pragma unroll
            for (int mt = 0; mt < 4; mt++) {
                const float blo = b2[mloc0 + wm + mt * 16 + grp];
                const float bhi = b2[mloc0 + wm + mt * 16 + grp + 8];
                #pragma unroll
                for (int nf = 0; nf < 4; nf++) {
                    int m = wm + mt * 16 + grp;
                    int n = wn + nf * 8 + tg * 2;
                    uint32_t sw = (uint32_t)((m & 7) << 4);
                    uint32_t off = (uint32_t)(n * 2) ^ sw;
                    *(__half2*)(gsm + (uint32_t)m * 256 + off) =
                        h2(acc[mt][nf][0] + blo, acc[mt][nf][1] + blo);
                    *(__half2*)(gsm + (uint32_t)(m + 8) * 256 + off) =
                        h2(acc[mt][nf][2] + bhi, acc[mt][nf][3] + bhi);
                }
            }
            __syncthreads();
            #pragma unroll 1
            for (int it = 0; it < 16; it++) {
                const int r = rr + it * 8;
                uint32_t off = (uint32_t)(cc * 8) ^ (uint32_t)((r & 7) << 4);
                uint2 u = *(const uint2*)(gsm + (uint32_t)r * 256 + off);
                size_t a = ((size_t)((n0 >> 12) * CH + mloc0 + r)) * NPIX
                         + (n0 & (NPIX - 1)) + cc * 4;
                *(uint2*)&O2[a] = u;
            }
        } else {
            // ---- Q/K: stmatrix.trans into [n][m] fp16 staging (256B pitch, swizzled) ----
            const float* bp = (wtype == 0) ? b0 : b1;
            const float sc = (wtype == 0) ? scale : 1.0f;
            __half* Op = (wtype == 0) ? O0 : O1;

            // lane roles for x4: kk = matrix index, ii = row within matrix
            const int kk = lane >> 3, ii = lane & 7;
            const int nf_a = kk >> 1, hf_a = kk & 1;
            #pragma unroll
            for (int mt = 0; mt < 4; mt++) {
                const float blo = (bp[mloc0 + wm + mt * 16 + grp]) ;
                const float bhi = (bp[mloc0 + wm + mt * 16 + grp + 8]);
                // matrices 0..3 = (nf,half): (nf_base+0,lo),(nf_base+0,hi),(nf_base+1,lo),(nf_base+1,hi)
                uint32_t q0 = h2u(h2((acc[mt][0][0] + blo) * sc, (acc[mt][0][1] + blo) * sc));
                uint32_t q1 = h2u(h2((acc[mt][0][2] + bhi) * sc, (acc[mt][0][3] + bhi) * sc));
                uint32_t q2 = h2u(h2((acc[mt][1][0] + blo) * sc, (acc[mt][1][1] + blo) * sc));
                uint32_t q3 = h2u(h2((acc[mt][1][2] + bhi) * sc, (acc[mt][1][3] + bhi) * sc));
                uint32_t q4 = h2u(h2((acc[mt][2][0] + blo) * sc, (acc[mt][2][1] + blo) * sc));
                uint32_t q5 = h2u(h2((acc[mt][2][2] + bhi) * sc, (acc[mt][2][3] + bhi) * sc));
                uint32_t q6 = h2u(h2((acc[mt][3][0] + blo) * sc, (acc[mt][3][1] + blo) * sc));
                uint32_t q7 = h2u(h2((acc[mt][3][2] + bhi) * sc, (acc[mt][3][3] + bhi) * sc));

                const int mcol = wm + mt * 16 + hf_a * 8;      // m-column base of this lane's matrix
                uint32_t a0 = sbase + (uint32_t)(wn + nf_a * 8 + ii) * 256
                            + (uint32_t)((mcol * 2) ^ (ii << 4));
                STMAT4T(a0, q0, q1, q2, q3);                   // nf 0,1
                STMAT4T(a0 + 16 * 256, q4, q5, q6, q7);        // nf 2,3
            }
            __syncthreads();
            // read out: rows = n (0..127), 128 halves of m each; 16 threads/row, uint4
            const int rr2 = tid >> 4;       // 0..15
            const int c16 = tid & 15;       // 0..15
            #pragma unroll 1
            for (int it = 0; it < 8; it++) {
                const int nl = rr2 + it * 16;
                uint32_t off = (uint32_t)(c16 * 16) ^ (uint32_t)((nl & 7) << 4);
                uint4 u = *(const uint4*)(gsm + (uint32_t)nl * 256 + off);
                size_t a = ((size_t)n0 + nl) * CH + mloc0 + c16 * 8;
                *(uint4*)&Op[a] = u;
            }
        }
        return;
    }

    // -------- fp32 staging path (EPI_P) --------
    float* Sf = (float*)gsm;
    #pragma unroll
    for (int mt = 0; mt < 4; mt++) {
        #pragma unroll
        for (int nf = 0; nf < 4; nf++) {
            int m = wm + mt * 16 + grp;
            int n = wn + nf * 8 + tg * 2;
            Sf[m * 129 + n]           = acc[mt][nf][0];
            Sf[m * 129 + n + 1]       = acc[mt][nf][1];
            Sf[(m + 8) * 129 + n]     = acc[mt][nf][2];
            Sf[(m + 8) * 129 + n + 1] = acc[mt][nf][3];
        }
    }
    __syncthreads();

    #pragma unroll 1
    for (int it = 0; it < 16; it++) {
        const int r = rr + it * 8;
        const float bv = b0[m0 + r];
        size_t a = ((size_t)((n0 >> 12) * CH + m0 + r)) * NPIX
                 + (n0 & (NPIX - 1)) + cc * 4;
        float4 rd = *(const float4*)&resid[a];
        const float* s = &Sf[r * 129 + cc * 4];
        float4 o = make_float4(s[0] + bv + rd.x, s[1] + bv + rd.y,
                               s[2] + bv + rd.z, s[3] + bv + rd.w);
        *(float4*)&Ofp[a] = o;
    }
}

// -------------- softmax rows of fp16 scores -> attn fp16 --------------
__global__ void __launch_bounds__(256) softmax_kernel()
{
    const size_t row = blockIdx.x;       // 0 .. NFOLD-1
    const uint4* p = (const uint4*)(g_s + row * NPIX);   // 512 uint4 (8 halves each)
    uint4* oh = (uint4*)(g_at + row * NPIX);
    const int t = threadIdx.x;
    const int lane = t & 31, wid = t >> 5;

    float v[16];
    float mx = -1e30f;
    #pragma unroll
    for (int j = 0; j < 2; j++) {
        uint4 u = p[t + 256 * j];
        const uint32_t* q = (const uint32_t*)&u;
        #pragma unroll
        for (int w = 0; w < 4; w++) {
            float2 f = __half22float2(*(const __half2*)&q[w]);
            v[j * 8 + w * 2 + 0] = f.x;
            v[j * 8 + w * 2 + 1] = f.y;
            mx = fmaxf(mx, fmaxf(f.x, f.y));
        }
    }
    __shared__ float red[8];
    __shared__ float s_mx, s_sum;
    #pragma unroll
    for (int o = 16; o; o >>= 1) mx = fmaxf(mx, __shfl_xor_sync(0xffffffffu, mx, o));
    if (lane == 0) red[wid] = mx;
    __syncthreads();
    if (t == 0) {
        float m = red[0];
        #pragma unroll
        for (int i = 1; i < 8; i++) m = fmaxf(m, red[i]);
        s_mx = m;
    }
    __syncthreads();
    mx = s_mx;

    float sum = 0.f;
    #pragma unroll
    for (int i = 0; i < 16; i++) {
        v[i] = __expf(v[i] - mx);
        sum += v[i];
    }
    #pragma unroll
    for (int o = 16; o; o >>= 1) sum += __shfl_xor_sync(0xffffffffu, sum, o);
    if (lane == 0) red[wid] = sum;
    __syncthreads();
    if (t == 0) {
        float s = 0.f;
        #pragma unroll
        for (int i = 0; i < 8; i++) s += red[i];
        s_sum = s;
    }
    __syncthreads();
    const float inv = 1.0f / s_sum;

    #pragma unroll
    for (int j = 0; j < 2; j++) {
        uint4 u;
        uint32_t* q = (uint32_t*)&u;
        #pragma unroll
        for (int w = 0; w < 4; w++) {
            __half2 hh = h2(v[j * 8 + w * 2] * inv, v[j * 8 + w * 2 + 1] * inv);
            q[w] = *(uint32_t*)&hh;
        }
        oh[t + 256 * j] = u;
    }
}

// ------------------------- launcher -------------------------
extern "C" void kernel_launch(void* const* d_in, const int* in_sizes, int n_in,
                              void* d_out, int out_size)
{
    const float* x     = (const float*)d_in[0];
    const float* gamma = (const float*)d_in[1];
    const float* beta  = (const float*)d_in[2];
    const float* Wq    = (const float*)d_in[3];
    const float* bq    = (const float*)d_in[4];
    const float* Wk    = (const float*)d_in[5];
    const float* bk    = (const float*)d_in[6];
    const float* Wv    = (const float*)d_in[7];
    const float* bv    = (const float*)d_in[8];
    const float* Wo    = (const float*)d_in[9];
    const float* bo    = (const float*)d_in[10];
    float* out = (float*)d_out;

    void* p;
    __half *w, *hnT, *qT, *kT, *v, *at, *oT, *sh;
    cudaGetSymbolAddress(&p, g_w);    w   = (__half*)p;
    cudaGetSymbolAddress(&p, g_hnT);  hnT = (__half*)p;
    cudaGetSymbolAddress(&p, g_qT);   qT  = (__half*)p;
    cudaGetSymbolAddress(&p, g_kT);   kT  = (__half*)p;
    cudaGetSymbolAddress(&p, g_v);    v   = (__half*)p;
    cudaGetSymbolAddress(&p, g_at);   at  = (__half*)p;
    cudaGetSymbolAddress(&p, g_oT);   oT  = (__half*)p;
    cudaGetSymbolAddress(&p, g_s);    sh  = (__half*)p;

    cudaFuncSetAttribute(gemm_mma<EPI_QKV>, cudaFuncAttributeMaxDynamicSharedMemorySize, SMEM_GEMM);
    cudaFuncSetAttribute(gemm_mma<EPI_S>,   cudaFuncAttributeMaxDynamicSharedMemorySize, SMEM_GEMM);
    cudaFuncSetAttribute(gemm_mma<EPI_AV>,  cudaFuncAttributeMaxDynamicSharedMemorySize, SMEM_GEMM);
    cudaFuncSetAttribute(gemm_mma<EPI_P>,   cudaFuncAttributeMaxDynamicSharedMemorySize, SMEM_GEMM);

    const float scale = 1.0f / sqrtf((float)CH);
    const size_t WN = (size_t)CH * CH;

    // merged: weights fp32->fp16 (blocks 0..1023) + GroupNorm stats (1024..1087)
    preproc_kernel<<<1088, 256>>>(Wq, Wk, Wv, Wo, x);
    // transpose+normalize -> hnT
    tnc_kernel<<<dim3(NPIX / 32, CH / 32, BATCH), 256>>>(x, gamma, beta);

    // fused QKV GEMM: A = stacked W [1536, 512], B = hnT [NFOLD, 512]
    dim3 gQKV(NFOLD / 128, 3 * CH / 128, 1);     // 64 x 12 = 768 CTAs
    gemm_mma<EPI_QKV><<<gQKV, 256, SMEM_GEMM>>>(
        w, hnT, CH, 0, 0,
        qT, kT, v, nullptr, bq, bk, bv, nullptr, scale);

    // scores (scale folded into q) -> fp16
    dim3 gS(NPIX / 128, NPIX / 128, BATCH);      // 32 x 32 x 2 = 2048 CTAs
    gemm_mma<EPI_S><<<gS, 256, SMEM_GEMM>>>(
        qT, kT, CH, (size_t)NPIX * CH, (size_t)NPIX * CH,
        sh, nullptr, nullptr, nullptr, nullptr, nullptr, nullptr, nullptr, 0.f);

    // softmax -> attn fp16
    softmax_kernel<<<NFOLD, 256>>>();

    // AV: D[i,c] = sum_j attn[i,j] v[c,j] -> oT row-major [NFOLD, CH]
    dim3 gAV(CH / 128, NPIX / 128, BATCH);       // 4 x 32 x 2 = 256 CTAs
    gemm_mma<EPI_AV><<<gAV, 256, SMEM_GEMM>>>(
        at, v, NPIX, (size_t)NPIX * NPIX, (size_t)CH * NPIX,
        oT, nullptr, nullptr, nullptr, nullptr, nullptr, nullptr, nullptr, 0.f);

    // proj + bias + residual -> out
    dim3 gP(NFOLD / 128, CH / 128, 1);           // 64 x 4 = 256 CTAs
    gemm_mma<EPI_P><<<gP, 256, SMEM_GEMM>>>(
        w + 3 * WN, oT, CH, 0, 0,
        nullptr, nullptr, nullptr, out, bo, nullptr, nullptr, x, 0.f);

    (void)in_sizes; (void)n_in; (void)out_size;
}

// round 17
// speedup vs baseline: 1.4213x; 1.0467x over previous
#include <cuda_runtime.h>
#include <cuda_fp16.h>
#include <cstdint>
#include <cmath>

#define BATCH 2
#define CH    512
#define NPIX  4096
#define NFOLD (BATCH * NPIX)     // 8192
#define EPS   1e-6f

// ------------------------- scratch (device globals) -------------------------
static __device__ float2 g_stats[BATCH * 32];
static __device__ __half g_w[4 * CH * CH];                     // q,k,v,o stacked
static __device__ __half g_hnT[(size_t)NFOLD * CH];
static __device__ __half g_qT[(size_t)NFOLD * CH];
static __device__ __half g_kT[(size_t)NFOLD * CH];
static __device__ __half g_v[(size_t)BATCH * CH * NPIX];
static __device__ __half g_at[(size_t)BATCH * NPIX * NPIX];    // exp'd scores, 67 MB
static __device__ float  g_zpart[(size_t)NFOLD * 32];          // per-(row,tile) sums
static __device__ float  g_invz[NFOLD];
static __device__ __half g_oT[(size_t)NFOLD * CH];

// ------------------------- small helpers -------------------------
__device__ __forceinline__ void cp16(uint32_t s, const void* g) {
    asm volatile("cp.async.cg.shared.global [%0], [%1], 16;" :: "r"(s), "l"(g));
}

#define CP_COMMIT() asm volatile("cp.async.commit_group;" ::: "memory")

#define LDSM4(R, addr) \
    asm volatile("ldmatrix.sync.aligned.m8n8.x4.shared.b16 {%0,%1,%2,%3}, [%4];" \
        : "=r"((R)[0]), "=r"((R)[1]), "=r"((R)[2]), "=r"((R)[3]) : "r"(addr))

#define STMAT4T(addr, r0, r1, r2, r3) \
    asm volatile("stmatrix.sync.aligned.m8n8.x4.trans.shared.b16 [%0], {%1,%2,%3,%4};" \
        :: "r"(addr), "r"(r0), "r"(r1), "r"(r2), "r"(r3) : "memory")

#define MMA16816(D, A, B) \
    asm volatile("mma.sync.aligned.m16n8k16.row.col.f32.f16.f16.f32 " \
        "{%0,%1,%2,%3}, {%4,%5,%6,%7}, {%8,%9}, {%0,%1,%2,%3};" \
        : "+f"((D)[0]), "+f"((D)[1]), "+f"((D)[2]), "+f"((D)[3]) \
        : "r"((A)[0]), "r"((A)[1]), "r"((A)[2]), "r"((A)[3]), \
          "r"((B)[0]), "r"((B)[1]))

__device__ __forceinline__ uint32_t smem_u32(const void* p) {
    uint32_t a;
    asm("{ .reg .u64 t; cvta.to.shared.u64 t, %1; cvt.u32.u64 %0, t; }"
        : "=r"(a) : "l"(p));
    return a;
}

__device__ __forceinline__ __half2 h2(float a, float b) {
    return __halves2half2(__float2half_rn(a), __float2half_rn(b));
}

__device__ __forceinline__ uint32_t h2u(__half2 v) {
    return *(uint32_t*)&v;
}

// ---------- merged preproc: W fp32->fp16 (blocks 0..1023) + GroupNorm stats (1024..1087) ----------
__global__ void __launch_bounds__(256) preproc_kernel(
    const float* __restrict__ w0, const float* __restrict__ w1,
    const float* __restrict__ w2, const float* __restrict__ w3,
    const float* __restrict__ x)
{
    if (blockIdx.x < 1024) {
        const int wsel = blockIdx.x >> 8;
        const float* src = (wsel == 0) ? w0 : (wsel == 1) ? w1
                         : (wsel == 2) ? w2 : w3;
        int i = (blockIdx.x & 255) * 256 + threadIdx.x;
        float4 v = ((const float4*)src)[i];
        size_t e = (size_t)wsel * CH * CH + (size_t)i * 4;
        __half2* d = (__half2*)(g_w + e);
        d[0] = h2(v.x, v.y);
        d[1] = h2(v.z, v.w);
        return;
    }
    // GroupNorm stats
    const int bi = blockIdx.x - 1024;
    const int g = bi & 31, b = bi >> 5;
    const size_t base = ((size_t)b * CH + (size_t)g * 16) * NPIX;
    const float4* x4 = (const float4*)(x + base);
    const int n4 = 16 * NPIX / 4;

    float s = 0.f, ss = 0.f;
    for (int i = threadIdx.x; i < n4; i += 256) {
        float4 v = x4[i];
        s  += v.x + v.y + v.z + v.w;
        ss += v.x * v.x + v.y * v.y + v.z * v.z + v.w * v.w;
    }
    __shared__ float rs[8], rss[8];
    #pragma unroll
    for (int o = 16; o; o >>= 1) {
        s  += __shfl_xor_sync(0xffffffffu, s, o);
        ss += __shfl_xor_sync(0xffffffffu, ss, o);
    }
    const int lane = threadIdx.x & 31, wid = threadIdx.x >> 5;
    if (lane == 0) { rs[wid] = s; rss[wid] = ss; }
    __syncthreads();
    if (threadIdx.x == 0) {
        float ts = 0.f, tss = 0.f;
        #pragma unroll
        for (int i = 0; i < 8; i++) { ts += rs[i]; tss += rss[i]; }
        const float inv_n = 1.0f / (16 * NPIX);
        float mean = ts * inv_n;
        float var = tss * inv_n - mean * mean;
        g_stats[b * 32 + g] = make_float2(mean, rsqrtf(var + EPS));
    }
}

// ---------- transpose + normalize + fp16 convert:  x[b,c,n] -> hnT[b*N+n, c] ----------
__global__ void __launch_bounds__(256) tnc_kernel(
    const float* __restrict__ x, const float* __restrict__ gamma,
    const float* __restrict__ beta)
{
    __shared__ float tile[32][33];
    const int b = blockIdx.z;
    const int n0 = blockIdx.x * 32, c0 = blockIdx.y * 32;
    const int tx = threadIdx.x & 31, ty = threadIdx.x >> 5;   // 32 x 8

    #pragma unroll
    for (int j = 0; j < 4; j++) {
        int c = c0 + ty + j * 8;
        float2 st = g_stats[b * 32 + (c >> 4)];
        float gm = gamma[c] * st.y;
        float bt = beta[c] - st.x * gm;
        float v = x[((size_t)(b * CH + c)) * NPIX + n0 + tx];
        tile[ty + j * 8][tx] = v * gm + bt;
    }
    __syncthreads();
    #pragma unroll
    for (int j = 0; j < 4; j++) {
        int n = n0 + ty + j * 8;
        float v = tile[tx][ty + j * 8];
        size_t a = ((size_t)(b * NPIX + n)) * CH + c0 + tx;
        g_hnT[a] = __float2half_rn(v);
    }
}

// -------------- invZ reduce: invZ[row] = 1 / sum_tile zpart[row][tile] --------------
__global__ void __launch_bounds__(256) reduce_z_kernel()
{
    const int row = blockIdx.x * 256 + threadIdx.x;    // 0..NFOLD-1
    const float4* zp = (const float4*)(g_zpart + (size_t)row * 32);
    float s = 0.f;
    #pragma unroll
    for (int i = 0; i < 8; i++) {
        float4 v = zp[i];
        s += v.x + v.y + v.z + v.w;
    }
    g_invz[row] = 1.0f / s;
}

// ------------------------- mma.sync GEMM (fp16, 8 warps, 64x32 warp tile) -------------------------
// D[m,n] = sum_k A[m,k]*B[n,k], K-major fp16, fp32 acc.
// CTA: 128(M) x 128(N), K-chunk 64, XOR-swizzled 128B rows, 3-stage cp.async.
// 256 thr = 8 warps in 2(M) x 4(N); warp tile 64x32. __launch_bounds__(256,2).
#define OFF_B    16384
#define STAGE    32768
#define SMEM_GEMM (3 * STAGE)    // 98304

enum { EPI_QKV = 0, EPI_S = 1, EPI_AV = 2, EPI_P = 3 };

__device__ __forceinline__ void load_stage(
    uint32_t so, const __half* __restrict__ A, const __half* __restrict__ B,
    int K, int k0, int tid)
{
    #pragma unroll
    for (int j = 0; j < 8; j++) {
        int i = tid + j * 256;                 // 0..2047
        int r = (i >> 3) & 127;                // row within region
        int c = i & 7;                         // 16B unit
        const __half* src = ((j < 4) ? A : B) + r * K + k0 + c * 8;
        uint32_t dst = so + ((j < 4) ? 0u : (uint32_t)OFF_B)
                     + (uint32_t)r * 128 + (uint32_t)((c ^ (r & 7)) << 4);
        cp16(dst, src);
    }
}

__device__ __forceinline__ void compute_chunk(
    uint32_t so, int wm, int wn, int lane, float acc[4][4][4])
{
    const int ra = wm + (lane & 15);
    const int rb = wn + ((lane >> 4) << 3) + (lane & 7);
    const uint32_t a_row = so + (uint32_t)ra * 128;
    const uint32_t b_row = so + OFF_B + (uint32_t)rb * 128;
    const int ua = (lane >> 4);
    const int ub = ((lane >> 3) & 1);

    #pragma unroll
    for (int ks = 0; ks < 4; ks++) {
        const uint32_t a_sw = (uint32_t)(((2 * ks + ua) ^ (ra & 7)) << 4);
        const uint32_t b_sw = (uint32_t)(((2 * ks + ub) ^ (rb & 7)) << 4);
        uint32_t A0[4], A1[4], A2[4], A3[4], B0[4], B1[4];
        LDSM4(A0, a_row + a_sw);
        LDSM4(A1, a_row + a_sw + 16 * 128);
        LDSM4(A2, a_row + a_sw + 32 * 128);
        LDSM4(A3, a_row + a_sw + 48 * 128);
        LDSM4(B0, b_row + b_sw);
        LDSM4(B1, b_row + b_sw + 16 * 128);
        MMA16816(acc[0][0], A0, B0);  MMA16816(acc[0][1], A0, B0 + 2);
        MMA16816(acc[0][2], A0, B1);  MMA16816(acc[0][3], A0, B1 + 2);
        MMA16816(acc[1][0], A1, B0);  MMA16816(acc[1][1], A1, B0 + 2);
        MMA16816(acc[1][2], A1, B1);  MMA16816(acc[1][3], A1, B1 + 2);
        MMA16816(acc[2][0], A2, B0);  MMA16816(acc[2][1], A2, B0 + 2);
        MMA16816(acc[2][2], A2, B1);  MMA16816(acc[2][3], A2, B1 + 2);
        MMA16816(acc[3][0], A3, B0);  MMA16816(acc[3][1], A3, B0 + 2);
        MMA16816(acc[3][2], A3, B1);  MMA16816(acc[3][3], A3, B1 + 2);
    }
}

template<int EPI>
__global__ void __launch_bounds__(256, 2) gemm_mma(
    const __half* __restrict__ A, const __half* __restrict__ B,
    int K, size_t Az, size_t Bz,
    __half* __restrict__ O0, __half* __restrict__ O1, __half* __restrict__ O2,
    float* __restrict__ Ofp,
    const float* __restrict__ b0, const float* __restrict__ b1,
    const float* __restrict__ b2,
    const float* __restrict__ resid, float scale)
{
    extern __shared__ __align__(16) uint8_t gsm[];
    const uint32_t sbase = smem_u32(gsm);
    const int tid = threadIdx.x, lane = tid & 31, wid = tid >> 5;
    const int wm = (wid >> 2) * 64, wn = (wid & 3) * 32;
    const int bz = blockIdx.z;
    const int m0 = blockIdx.y * 128, n0 = blockIdx.x * 128;

    const __half* Ap = A + (size_t)bz * Az + (size_t)m0 * K;
    const __half* Bp = B + (size_t)bz * Bz + (size_t)n0 * K;

    const int NT = K / 64;
    float acc[4][4][4] = {};

    load_stage(sbase + 0 * STAGE, Ap, Bp, K, 0, tid);  CP_COMMIT();
    load_stage(sbase + 1 * STAGE, Ap, Bp, K, 64, tid); CP_COMMIT();

    int s2 = 2, s0 = 0;
    for (int t = 0; t < NT; t++) {
        if (t + 1 < NT) {
            asm volatile("cp.async.wait_group 1;" ::: "memory");
        } else {
            asm volatile("cp.async.wait_group 0;" ::: "memory");
        }
        __syncthreads();
        if (t + 2 < NT) {
            load_stage(sbase + (uint32_t)s2 * STAGE, Ap, Bp, K, (t + 2) * 64, tid);
            CP_COMMIT();
        }
        compute_chunk(sbase + (uint32_t)s0 * STAGE, wm, wn, lane, acc);
        s0++; if (s0 == 3) s0 = 0;
        s2++; if (s2 == 3) s2 = 0;
    }
    __syncthreads();

    const int grp = lane >> 2, tg = lane & 3;
    const int rr = tid >> 5;        // 0..7 (warp id)
    const int cc = tid & 31;        // 0..31 (lane)

    if (EPI == EPI_S || EPI == EPI_AV) {
        // fp16 staging, 256B pitch, XOR swizzle phys = n*2 ^ ((m&7)<<4).
        // For AV: multiply by invZ[row] BEFORE fp16 rounding (unnormalized sums overflow fp16).
        #pragma unroll
        for (int mt = 0; mt < 4; mt++) {
            float izlo = 1.f, izhi = 1.f;
            if (EPI == EPI_AV) {
                izlo = g_invz[(size_t)bz * NPIX + m0 + wm + mt * 16 + grp];
                izhi = g_invz[(size_t)bz * NPIX + m0 + wm + mt * 16 + grp + 8];
            }
            #pragma unroll
            for (int nf = 0; nf < 4; nf++) {
                int m = wm + mt * 16 + grp;
                int n = wn + nf * 8 + tg * 2;
                uint32_t sw = (uint32_t)((m & 7) << 4);
                uint32_t off = (uint32_t)(n * 2) ^ sw;
                *(__half2*)(gsm + (uint32_t)m * 256 + off) =
                    h2(acc[mt][nf][0] * izlo, acc[mt][nf][1] * izlo);
                *(__half2*)(gsm + (uint32_t)(m + 8) * 256 + off) =
                    h2(acc[mt][nf][2] * izhi, acc[mt][nf][3] * izhi);
            }
        }
        __syncthreads();
        #pragma unroll 1
        for (int it = 0; it < 16; it++) {
            const int r = rr + it * 8;
            uint32_t off = (uint32_t)(cc * 8) ^ (uint32_t)((r & 7) << 4);
            uint2 u = *(const uint2*)(gsm + (uint32_t)r * 256 + off);
            if (EPI == EPI_S) {
                // exp + per-(row,tile) partial sum; store exp'd fp16 to O0 (= g_at)
                float2 f0 = __half22float2(*(const __half2*)&u.x);
                float2 f1 = __half22float2(*(const __half2*)&u.y);
                float e0 = __expf(fminf(f0.x, 30.f));
                float e1 = __expf(fminf(f0.y, 30.f));
                float e2 = __expf(fminf(f1.x, 30.f));
                float e3 = __expf(fminf(f1.y, 30.f));
                uint2 eu;
                eu.x = h2u(h2(e0, e1));
                eu.y = h2u(h2(e2, e3));
                size_t a = ((size_t)bz * NPIX + m0 + r) * NPIX + n0 + cc * 4;
                *(uint2*)&O0[a] = eu;
                float ps = e0 + e1 + e2 + e3;
                #pragma unroll
                for (int o = 16; o; o >>= 1)
                    ps += __shfl_xor_sync(0xffffffffu, ps, o);
                if (cc == 0)
                    g_zpart[((size_t)bz * NPIX + m0 + r) * 32 + (n0 >> 7)] = ps;
            } else {
                size_t a = ((size_t)bz * NPIX + m0 + r) * CH + n0 + cc * 4;
                *(uint2*)&O0[a] = u;
            }
        }
        return;
    }

    if (EPI == EPI_QKV) {
        const int wtype = m0 >> 9;      // 0=q,1=k,2=v
        const int mloc0 = m0 & (CH - 1);

        if (wtype == 2) {
            // ---- V: row-major fp16 staging with bias ----
            #pragma unroll
            for (int mt = 0; mt < 4; mt++) {
                const float blo = b2[mloc0 + wm + mt * 16 + grp];
                const float bhi = b2[mloc0 + wm + mt * 16 + grp + 8];
                #pragma unroll
                for (int nf = 0; nf < 4; nf++) {
                    int m = wm + mt * 16 + grp;
                    int n = wn + nf * 8 + tg * 2;
                    uint32_t sw = (uint32_t)((m & 7) << 4);
                    uint32_t off = (uint32_t)(n * 2) ^ sw;
                    *(__half2*)(gsm + (uint32_t)m * 256 + off) =
                        h2(acc[mt][nf][0] + blo, acc[mt][nf][1] + blo);
                    *(__half2*)(gsm + (uint32_t)(m + 8) * 256 + off) =
                        h2(acc[mt][nf][2] + bhi, acc[mt][nf][3] + bhi);
                }
            }
            __syncthreads();
            #pragma unroll 1
            for (int it = 0; it < 16; it++) {
                const int r = rr + it * 8;
                uint32_t off = (uint32_t)(cc * 8) ^ (uint32_t)((r & 7) << 4);
                uint2 u = *(const uint2*)(gsm + (uint32_t)r * 256 + off);
                size_t a = ((size_t)((n0 >> 12) * CH + mloc0 + r)) * NPIX
                         + (n0 & (NPIX - 1)) + cc * 4;
                *(uint2*)&O2[a] = u;
            }
        } else {
            // ---- Q/K: stmatrix.trans into [n][m] fp16 staging (256B pitch, swizzled) ----
            const float* bp = (wtype == 0) ? b0 : b1;
            const float sc = (wtype == 0) ? scale : 1.0f;
            __half* Op = (wtype == 0) ? O0 : O1;

            const int kk = lane >> 3, ii = lane & 7;
            const int nf_a = kk >> 1, hf_a = kk & 1;
            #pragma unroll
            for (int mt = 0; mt < 4; mt++) {
                const float blo = (bp[mloc0 + wm + mt * 16 + grp]);
                const float bhi = (bp[mloc0 + wm + mt * 16 + grp + 8]);
                uint32_t q0 = h2u(h2((acc[mt][0][0] + blo) * sc, (acc[mt][0][1] + blo) * sc));
                uint32_t q1 = h2u(h2((acc[mt][0][2] + bhi) * sc, (acc[mt][0][3] + bhi) * sc));
                uint32_t q2 = h2u(h2((acc[mt][1][0] + blo) * sc, (acc[mt][1][1] + blo) * sc));
                uint32_t q3 = h2u(h2((acc[mt][1][2] + bhi) * sc, (acc[mt][1][3] + bhi) * sc));
                uint32_t q4 = h2u(h2((acc[mt][2][0] + blo) * sc, (acc[mt][2][1] + blo) * sc));
                uint32_t q5 = h2u(h2((acc[mt][2][2] + bhi) * sc, (acc[mt][2][3] + bhi) * sc));
                uint32_t q6 = h2u(h2((acc[mt][3][0] + blo) * sc, (acc[mt][3][1] + blo) * sc));
                uint32_t q7 = h2u(h2((acc[mt][3][2] + bhi) * sc, (acc[mt][3][3] + bhi) * sc));

                const int mcol = wm + mt * 16 + hf_a * 8;
                uint32_t a0 = sbase + (uint32_t)(wn + nf_a * 8 + ii) * 256
                            + (uint32_t)((mcol * 2) ^ (ii << 4));
                STMAT4T(a0, q0, q1, q2, q3);
                STMAT4T(a0 + 16 * 256, q4, q5, q6, q7);
            }
            __syncthreads();
            const int rr2 = tid >> 4;       // 0..15
            const int c16 = tid & 15;       // 0..15
            #pragma unroll 1
            for (int it = 0; it < 8; it++) {
                const int nl = rr2 + it * 16;
                uint32_t off = (uint32_t)(c16 * 16) ^ (uint32_t)((nl & 7) << 4);
                uint4 u = *(const uint4*)(gsm + (uint32_t)nl * 256 + off);
                size_t a = ((size_t)n0 + nl) * CH + mloc0 + c16 * 8;
                *(uint4*)&Op[a] = u;
            }
        }
        return;
    }

    // -------- fp32 staging path (EPI_P) --------
    float* Sf = (float*)gsm;
    #pragma unroll
    for (int mt = 0; mt < 4; mt++) {
        #pragma unroll
        for (int nf = 0; nf < 4; nf++) {
            int m = wm + mt * 16 + grp;
            int n = wn + nf * 8 + tg * 2;
            Sf[m * 129 + n]           = acc[mt][nf][0];
            Sf[m * 129 + n + 1]       = acc[mt][nf][1];
            Sf[(m + 8) * 129 + n]     = acc[mt][nf][2];
            Sf[(m + 8) * 129 + n + 1] = acc[mt][nf][3];
        }
    }
    __syncthreads();

    #pragma unroll 1
    for (int it = 0; it < 16; it++) {
        const int r = rr + it * 8;
        const float bv = b0[m0 + r];
        size_t a = ((size_t)((n0 >> 12) * CH + m0 + r)) * NPIX
                 + (n0 & (NPIX - 1)) + cc * 4;
        float4 rd = *(const float4*)&resid[a];
        const float* s = &Sf[r * 129 + cc * 4];
        float4 o = make_float4(s[0] + bv + rd.x, s[1] + bv + rd.y,
                               s[2] + bv + rd.z, s[3] + bv + rd.w);
        *(float4*)&Ofp[a] = o;
    }
}

// ------------------------- launcher -------------------------
extern "C" void kernel_launch(void* const* d_in, const int* in_sizes, int n_in,
                              void* d_out, int out_size)
{
    const float* x     = (const float*)d_in[0];
    const float* gamma = (const float*)d_in[1];
    const float* beta  = (const float*)d_in[2];
    const float* Wq    = (const float*)d_in[3];
    const float* bq    = (const float*)d_in[4];
    const float* Wk    = (const float*)d_in[5];
    const float* bk    = (const float*)d_in[6];
    const float* Wv    = (const float*)d_in[7];
    const float* bv    = (const float*)d_in[8];
    const float* Wo    = (const float*)d_in[9];
    const float* bo    = (const float*)d_in[10];
    float* out = (float*)d_out;

    void* p;
    __half *w, *hnT, *qT, *kT, *v, *at, *oT;
    cudaGetSymbolAddress(&p, g_w);    w   = (__half*)p;
    cudaGetSymbolAddress(&p, g_hnT);  hnT = (__half*)p;
    cudaGetSymbolAddress(&p, g_qT);   qT  = (__half*)p;
    cudaGetSymbolAddress(&p, g_kT);   kT  = (__half*)p;
    cudaGetSymbolAddress(&p, g_v);    v   = (__half*)p;
    cudaGetSymbolAddress(&p, g_at);   at  = (__half*)p;
    cudaGetSymbolAddress(&p, g_oT);   oT  = (__half*)p;

    cudaFuncSetAttribute(gemm_mma<EPI_QKV>, cudaFuncAttributeMaxDynamicSharedMemorySize, SMEM_GEMM);
    cudaFuncSetAttribute(gemm_mma<EPI_S>,   cudaFuncAttributeMaxDynamicSharedMemorySize, SMEM_GEMM);
    cudaFuncSetAttribute(gemm_mma<EPI_AV>,  cudaFuncAttributeMaxDynamicSharedMemorySize, SMEM_GEMM);
    cudaFuncSetAttribute(gemm_mma<EPI_P>,   cudaFuncAttributeMaxDynamicSharedMemorySize, SMEM_GEMM);

    const float scale = 1.0f / sqrtf((float)CH);
    const size_t WN = (size_t)CH * CH;

    // merged: weights fp32->fp16 (blocks 0..1023) + GroupNorm stats (1024..1087)
    preproc_kernel<<<1088, 256>>>(Wq, Wk, Wv, Wo, x);
    // transpose+normalize -> hnT
    tnc_kernel<<<dim3(NPIX / 32, CH / 32, BATCH), 256>>>(x, gamma, beta);

    // fused QKV GEMM: A = stacked W [1536, 512], B = hnT [NFOLD, 512]
    dim3 gQKV(NFOLD / 128, 3 * CH / 128, 1);     // 64 x 12 = 768 CTAs
    gemm_mma<EPI_QKV><<<gQKV, 256, SMEM_GEMM>>>(
        w, hnT, CH, 0, 0,
        qT, kT, v, nullptr, bq, bk, bv, nullptr, scale);

    // scores GEMM + exp + per-tile row sums -> g_at (exp'd) + g_zpart
    dim3 gS(NPIX / 128, NPIX / 128, BATCH);      // 32 x 32 x 2 = 2048 CTAs
    gemm_mma<EPI_S><<<gS, 256, SMEM_GEMM>>>(
        qT, kT, CH, (size_t)NPIX * CH, (size_t)NPIX * CH,
        at, nullptr, nullptr, nullptr, nullptr, nullptr, nullptr, nullptr, 0.f);

    // invZ[row] = 1 / sum_tile zpart
    reduce_z_kernel<<<NFOLD / 256, 256>>>();

    // AV: D[i,c] = (sum_j e[i,j] v[c,j]) * invZ[i] -> oT row-major [NFOLD, CH]
    dim3 gAV(CH / 128, NPIX / 128, BATCH);       // 4 x 32 x 2 = 256 CTAs
    gemm_mma<EPI_AV><<<gAV, 256, SMEM_GEMM>>>(
        at, v, NPIX, (size_t)NPIX * NPIX, (size_t)CH * NPIX,
        oT, nullptr, nullptr, nullptr, nullptr, nullptr, nullptr, nullptr, 0.f);

    // proj + bias + residual -> out
    dim3 gP(NFOLD / 128, CH / 128, 1);           // 64 x 4 = 256 CTAs
    gemm_mma<EPI_P><<<gP, 256, SMEM_GEMM>>>(
        w + 3 * WN, oT, CH, 0, 0,
        nullptr, nullptr, nullptr, out, bo, nullptr, nullptr, x, 0.f);

    (void)in_sizes; (void)n_in; (void)out_size;
}